// round 6
// baseline (speedup 1.0000x reference)
#include <cuda_runtime.h>
#include <cuda_bf16.h>
#include <cstdint>
#include <math.h>

// Problem constants
#define S    4096
#define H    1024
#define NH   16
#define HD   64
#define BS   64
#define NB   (S / BS)            // 64 blocks per axis
#define KDIM 1024

// ---------------------------------------------------------------------------
// Scratch (device globals; no allocation allowed)
// ---------------------------------------------------------------------------
__device__ float g_q[S * H];
__device__ float g_k[S * H];
__device__ float g_v[S * H];
__device__ float g_attn[S * H];
__device__ unsigned char g_cols[NB][NB];
__device__ int g_cnt[NB];

// ---------------------------------------------------------------------------
// Build block-level active-column lists from the dense [S,S] mask.
// Mask dtype auto-detected from first 4 bytes (block (0,0) is all-True diag):
//   float32: 0x3F800000 | uint8: 0x01010101 | bf16: 0x3F803F80 | else int32
// One thread per q-block row, serial over j => deterministic ordering.
// ---------------------------------------------------------------------------
__global__ void build_blockmask_kernel(const void* __restrict__ mask) {
    int i = threadIdx.x;
    if (i >= NB) return;
    unsigned int w0 = *(const unsigned int*)mask;
    int mode;
    if (w0 == 0x3F800000u)      mode = 0;  // float32
    else if (w0 == 0x01010101u) mode = 1;  // uint8/bool
    else if (w0 == 0x3F803F80u) mode = 2;  // bf16
    else                        mode = 3;  // int32

    int cnt = 0;
    for (int j = 0; j < NB; j++) {
        size_t idx = (size_t)(i * BS) * S + (size_t)(j * BS);
        bool on;
        if (mode == 0)      on = ((const float*)mask)[idx] != 0.0f;
        else if (mode == 1) on = ((const unsigned char*)mask)[idx] != 0;
        else if (mode == 2) on = __bfloat162float(((const __nv_bfloat16*)mask)[idx]) != 0.0f;
        else                on = ((const int*)mask)[idx] != 0;
        if (on) g_cols[i][cnt++] = (unsigned char)j;
    }
    g_cnt[i] = cnt;
}

// ---------------------------------------------------------------------------
// SGEMM: C[M,N] = A[M,K] @ B[N,K]^T + bias[N]
// BM=128, BN=128, BK=8, 256 threads, 8x8 per thread, float4 everywhere.
// Double-buffered smem: next k-tile's LDGs issue before the compute body,
// one __syncthreads per iteration. M,N multiples of 128; K multiple of 8.
// ---------------------------------------------------------------------------
#define GBM 128
#define GBN 128
#define GBK 8

__global__ __launch_bounds__(256) void gemm_nt_bias_kernel(
    const float* __restrict__ A, const float* __restrict__ B,
    const float* __restrict__ bias, float* __restrict__ C,
    int M, int N, int K)
{
    __shared__ __align__(16) float As[2][GBK][GBM];
    __shared__ __align__(16) float Bs[2][GBK][GBN];

    const int t  = threadIdx.x;
    const int bx = blockIdx.x;   // N tile
    const int by = blockIdx.y;   // M tile

    const int tx = t & 15;       // 0..15
    const int ty = t >> 4;       // 0..15

    // load mapping: each thread loads one float4 of A and one of B per k-tile
    const int ldRow = t >> 1;          // 0..127
    const int ldK   = (t & 1) * 4;     // 0 or 4

    const float* Ab = A + (size_t)(by * GBM + ldRow) * K;
    const float* Bb = B + (size_t)(bx * GBN + ldRow) * K;

    float acc[8][8];
    #pragma unroll
    for (int i = 0; i < 8; i++)
        #pragma unroll
        for (int j = 0; j < 8; j++) acc[i][j] = 0.0f;

    const int nkt = K / GBK;

    // prologue: tile 0 -> buffer 0
    {
        float4 av = *(const float4*)(Ab + ldK);
        float4 bv = *(const float4*)(Bb + ldK);
        As[0][ldK + 0][ldRow] = av.x;
        As[0][ldK + 1][ldRow] = av.y;
        As[0][ldK + 2][ldRow] = av.z;
        As[0][ldK + 3][ldRow] = av.w;
        Bs[0][ldK + 0][ldRow] = bv.x;
        Bs[0][ldK + 1][ldRow] = bv.y;
        Bs[0][ldK + 2][ldRow] = bv.z;
        Bs[0][ldK + 3][ldRow] = bv.w;
    }
    __syncthreads();

    for (int kt = 0; kt < nkt - 1; kt++) {
        const int cur = kt & 1;
        const int nxt = cur ^ 1;

        // issue next tile's global loads BEFORE compute (latency hidden)
        float4 av = *(const float4*)(Ab + (kt + 1) * GBK + ldK);
        float4 bv = *(const float4*)(Bb + (kt + 1) * GBK + ldK);

        #pragma unroll
        for (int k = 0; k < GBK; k++) {
            float a[8], b[8];
            *(float4*)&a[0] = *(const float4*)&As[cur][k][ty * 8 + 0];
            *(float4*)&a[4] = *(const float4*)&As[cur][k][ty * 8 + 4];
            *(float4*)&b[0] = *(const float4*)&Bs[cur][k][tx * 8 + 0];
            *(float4*)&b[4] = *(const float4*)&Bs[cur][k][tx * 8 + 4];
            #pragma unroll
            for (int i = 0; i < 8; i++)
                #pragma unroll
                for (int j = 0; j < 8; j++)
                    acc[i][j] = fmaf(a[i], b[j], acc[i][j]);
        }

        // store next tile into the other buffer (no one reads it this iter)
        As[nxt][ldK + 0][ldRow] = av.x;
        As[nxt][ldK + 1][ldRow] = av.y;
        As[nxt][ldK + 2][ldRow] = av.z;
        As[nxt][ldK + 3][ldRow] = av.w;
        Bs[nxt][ldK + 0][ldRow] = bv.x;
        Bs[nxt][ldK + 1][ldRow] = bv.y;
        Bs[nxt][ldK + 2][ldRow] = bv.z;
        Bs[nxt][ldK + 3][ldRow] = bv.w;
        __syncthreads();
    }

    // epilogue compute on last tile
    {
        const int cur = (nkt - 1) & 1;
        #pragma unroll
        for (int k = 0; k < GBK; k++) {
            float a[8], b[8];
            *(float4*)&a[0] = *(const float4*)&As[cur][k][ty * 8 + 0];
            *(float4*)&a[4] = *(const float4*)&As[cur][k][ty * 8 + 4];
            *(float4*)&b[0] = *(const float4*)&Bs[cur][k][tx * 8 + 0];
            *(float4*)&b[4] = *(const float4*)&Bs[cur][k][tx * 8 + 4];
            #pragma unroll
            for (int i = 0; i < 8; i++)
                #pragma unroll
                for (int j = 0; j < 8; j++)
                    acc[i][j] = fmaf(a[i], b[j], acc[i][j]);
        }
    }

    const int col0 = bx * GBN + tx * 8;
    float bb[8];
    *(float4*)&bb[0] = *(const float4*)(bias + col0 + 0);
    *(float4*)&bb[4] = *(const float4*)(bias + col0 + 4);

    #pragma unroll
    for (int i = 0; i < 8; i++) {
        float* Crow = C + (size_t)(by * GBM + ty * 8 + i) * N + col0;
        float4 o0 = make_float4(acc[i][0] + bb[0], acc[i][1] + bb[1],
                                acc[i][2] + bb[2], acc[i][3] + bb[3]);
        float4 o1 = make_float4(acc[i][4] + bb[4], acc[i][5] + bb[5],
                                acc[i][6] + bb[6], acc[i][7] + bb[7]);
        *(float4*)(Crow + 0) = o0;
        *(float4*)(Crow + 4) = o1;
    }
}

// ---------------------------------------------------------------------------
// Block-sparse flash attention.
// Grid: (NB, NH). 256 threads. Each CTA handles one (q-block, head).
// Thread mapping: r = tid>>2 (query row 0..63), q = tid&3 (quarter).
// Per K chunk of 32 rows: thread computes 8 score columns (c = q*8..q*8+7),
// and accumulates 16 output dims (d = q*16..q*16+15).
// Online softmax in exp2 domain (scale*log2(e) folded into Q load).
// ---------------------------------------------------------------------------
__global__ __launch_bounds__(256) void sparse_attn_kernel(
    const float* __restrict__ Q, const float* __restrict__ K,
    const float* __restrict__ V, float* __restrict__ Out)
{
    __shared__ __align__(16) float4 Qs4[64][17];
    __shared__ __align__(16) float4 Ks4[32][17];
    __shared__ __align__(16) float4 Vs4[32][17];
    __shared__ float Ps[64][33];

    const int qb   = blockIdx.x;
    const int head = blockIdx.y;
    const int tid  = threadIdx.x;
    const int r    = tid >> 2;   // 0..63
    const int q    = tid & 3;    // 0..3

    const float SCALE = 0.125f * 1.44269504088896340736f;  // hd^-0.5 * log2(e)

    // Load and scale Q block: 64 rows x 16 float4
    {
        const float* Qbase = Q + (size_t)(qb * BS) * H + head * HD;
        #pragma unroll
        for (int it = 0; it < 4; it++) {
            int f   = tid + 256 * it;      // 0..1023
            int row = f >> 4;
            int c4  = f & 15;
            float4 v = *(const float4*)(Qbase + (size_t)row * H + c4 * 4);
            v.x *= SCALE; v.y *= SCALE; v.z *= SCALE; v.w *= SCALE;
            Qs4[row][c4] = v;
        }
    }
    __syncthreads();

    float O[16];
    #pragma unroll
    for (int i = 0; i < 16; i++) O[i] = 0.0f;
    float m = -INFINITY;
    float l = 0.0f;

    const int cnt = g_cnt[qb];
    const int c0  = q * 8;

    for (int jj = 0; jj < cnt; jj++) {
        const int jblk = g_cols[qb][jj];
        #pragma unroll
        for (int half = 0; half < 2; half++) {
            const int kr0 = jblk * BS + half * 32;

            __syncthreads();  // protect K/V smem from previous chunk's readers
            {
                const float* Kbase = K + (size_t)kr0 * H + head * HD;
                const float* Vbase = V + (size_t)kr0 * H + head * HD;
                #pragma unroll
                for (int it = 0; it < 2; it++) {
                    int f   = tid + 256 * it;  // 0..511
                    int row = f >> 4;
                    int c4  = f & 15;
                    Ks4[row][c4] = *(const float4*)(Kbase + (size_t)row * H + c4 * 4);
                    Vs4[row][c4] = *(const float4*)(Vbase + (size_t)row * H + c4 * 4);
                }
            }
            __syncthreads();

            // scores for this thread's 8 columns
            float s[8];
            #pragma unroll
            for (int i = 0; i < 8; i++) s[i] = 0.0f;
            #pragma unroll
            for (int d4 = 0; d4 < 16; d4++) {
                float4 qv = Qs4[r][d4];
                #pragma unroll
                for (int i = 0; i < 8; i++) {
                    float4 kv = Ks4[c0 + i][d4];
                    s[i] = fmaf(qv.x, kv.x, s[i]);
                    s[i] = fmaf(qv.y, kv.y, s[i]);
                    s[i] = fmaf(qv.z, kv.z, s[i]);
                    s[i] = fmaf(qv.w, kv.w, s[i]);
                }
            }

            // online softmax (row max over 32 cols = 8 local + reduce over 4 lanes)
            float smax = s[0];
            #pragma unroll
            for (int i = 1; i < 8; i++) smax = fmaxf(smax, s[i]);
            smax = fmaxf(smax, __shfl_xor_sync(0xffffffffu, smax, 1));
            smax = fmaxf(smax, __shfl_xor_sync(0xffffffffu, smax, 2));
            float mnew  = fmaxf(m, smax);
            float alpha = exp2f(m - mnew);

            float lsum = 0.0f;
            #pragma unroll
            for (int i = 0; i < 8; i++) {
                float p = exp2f(s[i] - mnew);
                Ps[r][c0 + i] = p;
                lsum += p;
            }
            lsum += __shfl_xor_sync(0xffffffffu, lsum, 1);
            lsum += __shfl_xor_sync(0xffffffffu, lsum, 2);
            l = l * alpha + lsum;
            m = mnew;
            #pragma unroll
            for (int i = 0; i < 16; i++) O[i] *= alpha;
            __syncwarp();

            // O += P @ V for this thread's 16 dims
            #pragma unroll
            for (int c = 0; c < 32; c++) {
                float p = Ps[r][c];
                #pragma unroll
                for (int i4 = 0; i4 < 4; i4++) {
                    float4 v = Vs4[c][q * 4 + i4];
                    O[i4 * 4 + 0] = fmaf(p, v.x, O[i4 * 4 + 0]);
                    O[i4 * 4 + 1] = fmaf(p, v.y, O[i4 * 4 + 1]);
                    O[i4 * 4 + 2] = fmaf(p, v.z, O[i4 * 4 + 2]);
                    O[i4 * 4 + 3] = fmaf(p, v.w, O[i4 * 4 + 3]);
                }
            }
        }
    }

    // finalize + store
    const float inv = 1.0f / l;
    float* outp = Out + (size_t)(qb * BS + r) * H + head * HD + q * 16;
    #pragma unroll
    for (int i4 = 0; i4 < 4; i4++) {
        float4 o = make_float4(O[i4 * 4 + 0] * inv, O[i4 * 4 + 1] * inv,
                               O[i4 * 4 + 2] * inv, O[i4 * 4 + 3] * inv);
        *(float4*)(outp + i4 * 4) = o;
    }
}

// ---------------------------------------------------------------------------
// Launch
// Inputs (metadata order): hidden_states, wq, bq, wk, bk, wv, bv, wo, bo, mask
// ---------------------------------------------------------------------------
extern "C" void kernel_launch(void* const* d_in, const int* in_sizes, int n_in,
                              void* d_out, int out_size)
{
    const float* x    = (const float*)d_in[0];
    const float* wq   = (const float*)d_in[1];
    const float* bq   = (const float*)d_in[2];
    const float* wk   = (const float*)d_in[3];
    const float* bk   = (const float*)d_in[4];
    const float* wv   = (const float*)d_in[5];
    const float* bv   = (const float*)d_in[6];
    const float* wo   = (const float*)d_in[7];
    const float* bo   = (const float*)d_in[8];
    const void*  mask = (const void*)d_in[9];
    float* out = (float*)d_out;

    float *dq, *dk, *dv, *dattn;
    cudaGetSymbolAddress((void**)&dq, g_q);
    cudaGetSymbolAddress((void**)&dk, g_k);
    cudaGetSymbolAddress((void**)&dv, g_v);
    cudaGetSymbolAddress((void**)&dattn, g_attn);

    build_blockmask_kernel<<<1, 64>>>(mask);

    dim3 gemmGrid(H / GBN, S / GBM);
    gemm_nt_bias_kernel<<<gemmGrid, 256>>>(x, wq, bq, dq, S, H, KDIM);
    gemm_nt_bias_kernel<<<gemmGrid, 256>>>(x, wk, bk, dk, S, H, KDIM);
    gemm_nt_bias_kernel<<<gemmGrid, 256>>>(x, wv, bv, dv, S, H, KDIM);

    dim3 attnGrid(NB, NH);
    sparse_attn_kernel<<<attnGrid, 256>>>(dq, dk, dv, dattn);

    gemm_nt_bias_kernel<<<gemmGrid, 256>>>(dattn, wo, bo, out, S, H, KDIM);
}

// round 7
// speedup vs baseline: 1.3947x; 1.3947x over previous
#include <cuda_runtime.h>
#include <cuda_bf16.h>
#include <cstdint>
#include <math.h>

// Problem constants
#define S    4096
#define H    1024
#define NH   16
#define HD   64
#define BS   64
#define NB   (S / BS)            // 64 blocks per axis
#define KDIM 1024

typedef unsigned long long ull;

// ---------------------------------------------------------------------------
// Scratch (device globals; no allocation allowed)
// ---------------------------------------------------------------------------
__device__ float g_q[S * H];
__device__ float g_k[S * H];
__device__ float g_v[S * H];
__device__ float g_attn[S * H];
__device__ unsigned char g_cols[NB][NB];
__device__ int g_cnt[NB];

// ---------------------------------------------------------------------------
// Packed f32x2 helpers (Blackwell sm_103a: 2x fp32 FMA per instruction)
// ---------------------------------------------------------------------------
__device__ __forceinline__ ull pack2(float x, float y) {
    ull r; asm("mov.b64 %0, {%1, %2};" : "=l"(r) : "f"(x), "f"(y)); return r;
}
__device__ __forceinline__ ull ffma2(ull a, ull b, ull c) {
    ull d; asm("fma.rn.f32x2 %0, %1, %2, %3;" : "=l"(d) : "l"(a), "l"(b), "l"(c)); return d;
}
__device__ __forceinline__ float2 unpack2(ull v) {
    float2 f; asm("mov.b64 {%0, %1}, %2;" : "=f"(f.x), "=f"(f.y) : "l"(v)); return f;
}

// ---------------------------------------------------------------------------
// Build block-level active-column lists from the dense [S,S] mask.
// Mask dtype auto-detected from first 4 bytes (block (0,0) is all-True diag):
//   float32: 0x3F800000 | uint8: 0x01010101 | bf16: 0x3F803F80 | else int32
// One thread per q-block row, serial over j => deterministic ordering.
// ---------------------------------------------------------------------------
__global__ void build_blockmask_kernel(const void* __restrict__ mask) {
    int i = threadIdx.x;
    if (i >= NB) return;
    unsigned int w0 = *(const unsigned int*)mask;
    int mode;
    if (w0 == 0x3F800000u)      mode = 0;  // float32
    else if (w0 == 0x01010101u) mode = 1;  // uint8/bool
    else if (w0 == 0x3F803F80u) mode = 2;  // bf16
    else                        mode = 3;  // int32

    int cnt = 0;
    for (int j = 0; j < NB; j++) {
        size_t idx = (size_t)(i * BS) * S + (size_t)(j * BS);
        bool on;
        if (mode == 0)      on = ((const float*)mask)[idx] != 0.0f;
        else if (mode == 1) on = ((const unsigned char*)mask)[idx] != 0;
        else if (mode == 2) on = __bfloat162float(((const __nv_bfloat16*)mask)[idx]) != 0.0f;
        else                on = ((const int*)mask)[idx] != 0;
        if (on) g_cols[i][cnt++] = (unsigned char)j;
    }
    g_cnt[i] = cnt;
}

// ---------------------------------------------------------------------------
// SGEMM: C[M,N] = A[M,K] @ B[N,K]^T + bias[N]
// BM=128, BN=128, BK=8, 256 threads, 8x8 per thread.
// Inner product uses packed fma.rn.f32x2 (FFMA2): 32 packed FMAs per k-step
// instead of 64 scalar FFMA. Double-buffered smem, one barrier per k-tile.
// ---------------------------------------------------------------------------
#define GBM 128
#define GBN 128
#define GBK 8

__global__ __launch_bounds__(256) void gemm_nt_bias_kernel(
    const float* __restrict__ A, const float* __restrict__ B,
    const float* __restrict__ bias, float* __restrict__ C,
    int M, int N, int K)
{
    __shared__ __align__(16) float As[2][GBK][GBM];
    __shared__ __align__(16) float Bs[2][GBK][GBN];

    const int t  = threadIdx.x;
    const int bx = blockIdx.x;   // N tile
    const int by = blockIdx.y;   // M tile

    const int tx = t & 15;       // 0..15
    const int ty = t >> 4;       // 0..15

    const int ldRow = t >> 1;          // 0..127
    const int ldK   = (t & 1) * 4;     // 0 or 4

    const float* Ab = A + (size_t)(by * GBM + ldRow) * K;
    const float* Bb = B + (size_t)(bx * GBN + ldRow) * K;

    ull acc2[8][4];
    #pragma unroll
    for (int i = 0; i < 8; i++)
        #pragma unroll
        for (int j = 0; j < 4; j++) acc2[i][j] = 0ull;

    const int nkt = K / GBK;

    // prologue: tile 0 -> buffer 0
    {
        float4 av = *(const float4*)(Ab + ldK);
        float4 bv = *(const float4*)(Bb + ldK);
        As[0][ldK + 0][ldRow] = av.x;
        As[0][ldK + 1][ldRow] = av.y;
        As[0][ldK + 2][ldRow] = av.z;
        As[0][ldK + 3][ldRow] = av.w;
        Bs[0][ldK + 0][ldRow] = bv.x;
        Bs[0][ldK + 1][ldRow] = bv.y;
        Bs[0][ldK + 2][ldRow] = bv.z;
        Bs[0][ldK + 3][ldRow] = bv.w;
    }
    __syncthreads();

    for (int kt = 0; kt < nkt - 1; kt++) {
        const int cur = kt & 1;
        const int nxt = cur ^ 1;

        // issue next tile's global loads BEFORE compute (latency hidden)
        float4 av = *(const float4*)(Ab + (kt + 1) * GBK + ldK);
        float4 bv = *(const float4*)(Bb + (kt + 1) * GBK + ldK);

        #pragma unroll
        for (int k = 0; k < GBK; k++) {
            float a[8];
            *(float4*)&a[0] = *(const float4*)&As[cur][k][ty * 8 + 0];
            *(float4*)&a[4] = *(const float4*)&As[cur][k][ty * 8 + 4];
            float4 b03 = *(const float4*)&Bs[cur][k][tx * 8 + 0];
            float4 b47 = *(const float4*)&Bs[cur][k][tx * 8 + 4];
            ull bb0 = pack2(b03.x, b03.y);
            ull bb1 = pack2(b03.z, b03.w);
            ull bb2 = pack2(b47.x, b47.y);
            ull bb3 = pack2(b47.z, b47.w);
            #pragma unroll
            for (int i = 0; i < 8; i++) {
                ull ai = pack2(a[i], a[i]);
                acc2[i][0] = ffma2(ai, bb0, acc2[i][0]);
                acc2[i][1] = ffma2(ai, bb1, acc2[i][1]);
                acc2[i][2] = ffma2(ai, bb2, acc2[i][2]);
                acc2[i][3] = ffma2(ai, bb3, acc2[i][3]);
            }
        }

        As[nxt][ldK + 0][ldRow] = av.x;
        As[nxt][ldK + 1][ldRow] = av.y;
        As[nxt][ldK + 2][ldRow] = av.z;
        As[nxt][ldK + 3][ldRow] = av.w;
        Bs[nxt][ldK + 0][ldRow] = bv.x;
        Bs[nxt][ldK + 1][ldRow] = bv.y;
        Bs[nxt][ldK + 2][ldRow] = bv.z;
        Bs[nxt][ldK + 3][ldRow] = bv.w;
        __syncthreads();
    }

    // epilogue compute on last tile
    {
        const int cur = (nkt - 1) & 1;
        #pragma unroll
        for (int k = 0; k < GBK; k++) {
            float a[8];
            *(float4*)&a[0] = *(const float4*)&As[cur][k][ty * 8 + 0];
            *(float4*)&a[4] = *(const float4*)&As[cur][k][ty * 8 + 4];
            float4 b03 = *(const float4*)&Bs[cur][k][tx * 8 + 0];
            float4 b47 = *(const float4*)&Bs[cur][k][tx * 8 + 4];
            ull bb0 = pack2(b03.x, b03.y);
            ull bb1 = pack2(b03.z, b03.w);
            ull bb2 = pack2(b47.x, b47.y);
            ull bb3 = pack2(b47.z, b47.w);
            #pragma unroll
            for (int i = 0; i < 8; i++) {
                ull ai = pack2(a[i], a[i]);
                acc2[i][0] = ffma2(ai, bb0, acc2[i][0]);
                acc2[i][1] = ffma2(ai, bb1, acc2[i][1]);
                acc2[i][2] = ffma2(ai, bb2, acc2[i][2]);
                acc2[i][3] = ffma2(ai, bb3, acc2[i][3]);
            }
        }
    }

    const int col0 = bx * GBN + tx * 8;
    float bb[8];
    *(float4*)&bb[0] = *(const float4*)(bias + col0 + 0);
    *(float4*)&bb[4] = *(const float4*)(bias + col0 + 4);

    #pragma unroll
    for (int i = 0; i < 8; i++) {
        float2 p0 = unpack2(acc2[i][0]);
        float2 p1 = unpack2(acc2[i][1]);
        float2 p2 = unpack2(acc2[i][2]);
        float2 p3 = unpack2(acc2[i][3]);
        float* Crow = C + (size_t)(by * GBM + ty * 8 + i) * N + col0;
        float4 o0 = make_float4(p0.x + bb[0], p0.y + bb[1],
                                p1.x + bb[2], p1.y + bb[3]);
        float4 o1 = make_float4(p2.x + bb[4], p2.y + bb[5],
                                p3.x + bb[6], p3.y + bb[7]);
        *(float4*)(Crow + 0) = o0;
        *(float4*)(Crow + 4) = o1;
    }
}

// ---------------------------------------------------------------------------
// Block-sparse flash attention, full 64-col blocks, conflict-free LDS.
// Grid: (NB, NH). 256 threads. CTA = one (q-block, head).
// Mapping: r = tid>>2 (query row), q = tid&3 (quad lane).
// Thread computes score cols c = 4i+q (i=0..15)  -> quad addresses stride one
// row (68/64 floats -> 4 banks apart -> conflict-free).
// Thread accumulates output float4 chunks d4 = 4*i4+q (i4=0..3).
// P exchanged within quad via __shfl (no smem Ps).
// Dynamic smem: Q[64][17] + K[64][17] + V[64][16] float4 = 51200 B.
// ---------------------------------------------------------------------------
#define ATTN_SMEM ((64 * 17 + 64 * 17 + 64 * 16) * 16)

__global__ __launch_bounds__(256) void sparse_attn_kernel(
    const float* __restrict__ Q, const float* __restrict__ K,
    const float* __restrict__ V, float* __restrict__ Out)
{
    extern __shared__ float4 dsm[];
    float4* Qs = dsm;                 // [64][17]
    float4* Ks = dsm + 64 * 17;       // [64][17]
    float4* Vs = dsm + 2 * 64 * 17;   // [64][16]

    const int qb   = blockIdx.x;
    const int head = blockIdx.y;
    const int tid  = threadIdx.x;
    const int r    = tid >> 2;   // 0..63
    const int q    = tid & 3;    // 0..3

    const float SCALE = 0.125f * 1.44269504088896340736f;  // hd^-0.5 * log2(e)

    // Load and scale Q block: 64 rows x 16 float4
    {
        const float* Qbase = Q + (size_t)(qb * BS) * H + head * HD;
        #pragma unroll
        for (int it = 0; it < 4; it++) {
            int f   = tid + 256 * it;      // 0..1023
            int row = f >> 4;
            int c4  = f & 15;
            float4 v = *(const float4*)(Qbase + (size_t)row * H + c4 * 4);
            v.x *= SCALE; v.y *= SCALE; v.z *= SCALE; v.w *= SCALE;
            Qs[row * 17 + c4] = v;
        }
    }

    float O[16];
    #pragma unroll
    for (int i = 0; i < 16; i++) O[i] = 0.0f;
    float m = -INFINITY;
    float l = 0.0f;

    const int cnt = g_cnt[qb];

    for (int jj = 0; jj < cnt; jj++) {
        const int kr0 = g_cols[qb][jj] * BS;

        __syncthreads();  // Q visible (1st iter) / prev chunk's readers done
        {
            const float* Kb = K + (size_t)kr0 * H + head * HD;
            const float* Vb = V + (size_t)kr0 * H + head * HD;
            #pragma unroll
            for (int it = 0; it < 4; it++) {
                int f   = tid + 256 * it;  // 0..1023
                int row = f >> 4;
                int c4  = f & 15;
                Ks[row * 17 + c4] = *(const float4*)(Kb + (size_t)row * H + c4 * 4);
                Vs[row * 16 + c4] = *(const float4*)(Vb + (size_t)row * H + c4 * 4);
            }
        }
        __syncthreads();

        // scores: 16 cols (c = 4i+q), full 64-dim dot from smem
        float s[16];
        #pragma unroll
        for (int i = 0; i < 16; i++) s[i] = 0.0f;
        #pragma unroll
        for (int d4 = 0; d4 < 16; d4++) {
            float4 qv = Qs[r * 17 + d4];
            #pragma unroll
            for (int i = 0; i < 16; i++) {
                float4 kv = Ks[(4 * i + q) * 17 + d4];
                s[i] = fmaf(qv.x, kv.x, s[i]);
                s[i] = fmaf(qv.y, kv.y, s[i]);
                s[i] = fmaf(qv.z, kv.z, s[i]);
                s[i] = fmaf(qv.w, kv.w, s[i]);
            }
        }

        // online softmax over the 64 cols (16 local + quad reduce)
        float smax = s[0];
        #pragma unroll
        for (int i = 1; i < 16; i++) smax = fmaxf(smax, s[i]);
        smax = fmaxf(smax, __shfl_xor_sync(0xffffffffu, smax, 1));
        smax = fmaxf(smax, __shfl_xor_sync(0xffffffffu, smax, 2));
        float mnew  = fmaxf(m, smax);
        float alpha = exp2f(m - mnew);

        float lsum = 0.0f;
        #pragma unroll
        for (int i = 0; i < 16; i++) {
            s[i] = exp2f(s[i] - mnew);   // s becomes p
            lsum += s[i];
        }
        lsum += __shfl_xor_sync(0xffffffffu, lsum, 1);
        lsum += __shfl_xor_sync(0xffffffffu, lsum, 2);
        l = l * alpha + lsum;
        m = mnew;
        #pragma unroll
        for (int i = 0; i < 16; i++) O[i] *= alpha;

        // O += P @ V ; p for col 4i+qq fetched from quad lane qq
        #pragma unroll
        for (int i = 0; i < 16; i++) {
            #pragma unroll
            for (int qq = 0; qq < 4; qq++) {
                float pc = __shfl_sync(0xffffffffu, s[i], qq, 4);
                const int c = 4 * i + qq;
                #pragma unroll
                for (int i4 = 0; i4 < 4; i4++) {
                    float4 vv = Vs[c * 16 + 4 * i4 + q];
                    O[i4 * 4 + 0] = fmaf(pc, vv.x, O[i4 * 4 + 0]);
                    O[i4 * 4 + 1] = fmaf(pc, vv.y, O[i4 * 4 + 1]);
                    O[i4 * 4 + 2] = fmaf(pc, vv.z, O[i4 * 4 + 2]);
                    O[i4 * 4 + 3] = fmaf(pc, vv.w, O[i4 * 4 + 3]);
                }
            }
        }
    }

    // finalize + store (thread owns float4 chunks d4 = 4*i4+q)
    const float inv = 1.0f / l;
    float* outp = Out + (size_t)(qb * BS + r) * H + head * HD;
    #pragma unroll
    for (int i4 = 0; i4 < 4; i4++) {
        float4 o = make_float4(O[i4 * 4 + 0] * inv, O[i4 * 4 + 1] * inv,
                               O[i4 * 4 + 2] * inv, O[i4 * 4 + 3] * inv);
        *(float4*)(outp + (4 * i4 + q) * 4) = o;
    }
}

// ---------------------------------------------------------------------------
// Launch
// Inputs (metadata order): hidden_states, wq, bq, wk, bk, wv, bv, wo, bo, mask
// ---------------------------------------------------------------------------
extern "C" void kernel_launch(void* const* d_in, const int* in_sizes, int n_in,
                              void* d_out, int out_size)
{
    const float* x    = (const float*)d_in[0];
    const float* wq   = (const float*)d_in[1];
    const float* bq   = (const float*)d_in[2];
    const float* wk   = (const float*)d_in[3];
    const float* bk   = (const float*)d_in[4];
    const float* wv   = (const float*)d_in[5];
    const float* bv   = (const float*)d_in[6];
    const float* wo   = (const float*)d_in[7];
    const float* bo   = (const float*)d_in[8];
    const void*  mask = (const void*)d_in[9];
    float* out = (float*)d_out;

    float *dq, *dk, *dv, *dattn;
    cudaGetSymbolAddress((void**)&dq, g_q);
    cudaGetSymbolAddress((void**)&dk, g_k);
    cudaGetSymbolAddress((void**)&dv, g_v);
    cudaGetSymbolAddress((void**)&dattn, g_attn);

    cudaFuncSetAttribute(sparse_attn_kernel,
                         cudaFuncAttributeMaxDynamicSharedMemorySize, ATTN_SMEM);

    build_blockmask_kernel<<<1, 64>>>(mask);

    dim3 gemmGrid(H / GBN, S / GBM);
    gemm_nt_bias_kernel<<<gemmGrid, 256>>>(x, wq, bq, dq, S, H, KDIM);
    gemm_nt_bias_kernel<<<gemmGrid, 256>>>(x, wk, bk, dk, S, H, KDIM);
    gemm_nt_bias_kernel<<<gemmGrid, 256>>>(x, wv, bv, dv, S, H, KDIM);

    dim3 attnGrid(NB, NH);
    sparse_attn_kernel<<<attnGrid, 256, ATTN_SMEM>>>(dq, dk, dv, dattn);

    gemm_nt_bias_kernel<<<gemmGrid, 256>>>(dattn, wo, bo, out, S, H, KDIM);
}

// round 10
// speedup vs baseline: 1.5558x; 1.1155x over previous
#include <cuda_runtime.h>
#include <cuda_bf16.h>
#include <cstdint>
#include <math.h>

// Problem constants
#define S    4096
#define H    1024
#define NH   16
#define HD   64
#define BS   64
#define NB   (S / BS)
#define KDIM 1024

// ---------------------------------------------------------------------------
// Scratch (device globals; no allocation allowed)
// ---------------------------------------------------------------------------
__device__ float g_q[S * H];
__device__ float g_k[S * H];
__device__ float g_v[S * H];
__device__ float g_attn[S * H];
__device__ unsigned char g_cols[NB][NB];
__device__ int g_cnt[NB];

// bf16 split operands (hi/lo)
__device__ __align__(16) __nv_bfloat16 g_xh[S * H];
__device__ __align__(16) __nv_bfloat16 g_xl[S * H];
__device__ __align__(16) __nv_bfloat16 g_ah[S * H];
__device__ __align__(16) __nv_bfloat16 g_al[S * H];
__device__ __align__(16) __nv_bfloat16 g_wqh[H * H];
__device__ __align__(16) __nv_bfloat16 g_wql[H * H];
__device__ __align__(16) __nv_bfloat16 g_wkh[H * H];
__device__ __align__(16) __nv_bfloat16 g_wkl[H * H];
__device__ __align__(16) __nv_bfloat16 g_wvh[H * H];
__device__ __align__(16) __nv_bfloat16 g_wvl[H * H];
__device__ __align__(16) __nv_bfloat16 g_woh[H * H];
__device__ __align__(16) __nv_bfloat16 g_wol[H * H];

// ---------------------------------------------------------------------------
// Baseline-PTX tensor-core primitives (sm_80+ ISA, compiles at compute_103)
// ---------------------------------------------------------------------------
__device__ __forceinline__ uint32_t smem_u32(const void* p) {
    uint32_t a;
    asm("{ .reg .u64 t; cvta.to.shared.u64 t, %1; cvt.u32.u64 %0, t; }"
        : "=r"(a) : "l"(p));
    return a;
}
__device__ __forceinline__ void ldsm_x4(uint32_t* r, uint32_t addr) {
    asm volatile("ldmatrix.sync.aligned.m8n8.x4.shared.b16 {%0,%1,%2,%3}, [%4];"
                 : "=r"(r[0]), "=r"(r[1]), "=r"(r[2]), "=r"(r[3]) : "r"(addr));
}
__device__ __forceinline__ void mma_bf16(float* d, const uint32_t* a,
                                         uint32_t b0, uint32_t b1) {
    asm volatile(
        "mma.sync.aligned.m16n8k16.row.col.f32.bf16.bf16.f32 "
        "{%0,%1,%2,%3}, {%4,%5,%6,%7}, {%8,%9}, {%0,%1,%2,%3};"
        : "+f"(d[0]), "+f"(d[1]), "+f"(d[2]), "+f"(d[3])
        : "r"(a[0]), "r"(a[1]), "r"(a[2]), "r"(a[3]), "r"(b0), "r"(b1));
}

// ---------------------------------------------------------------------------
// Block mask -> per-qblock active column lists
// ---------------------------------------------------------------------------
__global__ void build_blockmask_kernel(const void* __restrict__ mask) {
    int i = threadIdx.x;
    if (i >= NB) return;
    unsigned int w0 = *(const unsigned int*)mask;
    int mode;
    if (w0 == 0x3F800000u)      mode = 0;
    else if (w0 == 0x01010101u) mode = 1;
    else if (w0 == 0x3F803F80u) mode = 2;
    else                        mode = 3;

    int cnt = 0;
    for (int j = 0; j < NB; j++) {
        size_t idx = (size_t)(i * BS) * S + (size_t)(j * BS);
        bool on;
        if (mode == 0)      on = ((const float*)mask)[idx] != 0.0f;
        else if (mode == 1) on = ((const unsigned char*)mask)[idx] != 0;
        else if (mode == 2) on = __bfloat162float(((const __nv_bfloat16*)mask)[idx]) != 0.0f;
        else                on = ((const int*)mask)[idx] != 0;
        if (on) g_cols[i][cnt++] = (unsigned char)j;
    }
    g_cnt[i] = cnt;
}

// ---------------------------------------------------------------------------
// fp32 -> bf16 hi/lo split.  x = hi + lo + O(2^-17 x).
// ---------------------------------------------------------------------------
__global__ __launch_bounds__(256) void split_bf16_kernel(
    const float* __restrict__ src,
    __nv_bfloat16* __restrict__ hi, __nv_bfloat16* __restrict__ lo, int n4)
{
    int i = blockIdx.x * 256 + threadIdx.x;
    if (i >= n4) return;
    float4 v = ((const float4*)src)[i];
    __nv_bfloat16 h0 = __float2bfloat16(v.x);
    __nv_bfloat16 h1 = __float2bfloat16(v.y);
    __nv_bfloat16 h2 = __float2bfloat16(v.z);
    __nv_bfloat16 h3 = __float2bfloat16(v.w);
    __nv_bfloat16 l0 = __float2bfloat16(v.x - __bfloat162float(h0));
    __nv_bfloat16 l1 = __float2bfloat16(v.y - __bfloat162float(h1));
    __nv_bfloat16 l2 = __float2bfloat16(v.z - __bfloat162float(h2));
    __nv_bfloat16 l3 = __float2bfloat16(v.w - __bfloat162float(h3));
    __nv_bfloat162* hp = (__nv_bfloat162*)hi;
    __nv_bfloat162* lp = (__nv_bfloat162*)lo;
    hp[2 * i + 0] = __nv_bfloat162(h0, h1);
    hp[2 * i + 1] = __nv_bfloat162(h2, h3);
    lp[2 * i + 0] = __nv_bfloat162(l0, l1);
    lp[2 * i + 1] = __nv_bfloat162(l2, l3);
}

// ---------------------------------------------------------------------------
// mma.sync bf16-split GEMM: C[M,N] = A @ B^T + bias (fp32-accurate, 3 terms).
// CTA 128x128, 8 warps (2 M x 4 N), warp tile 64x32, k-tile 32.
// Smem pitch 40 bf16 (80B): ldmatrix row addresses hit 8 distinct bank quads.
// Grid: (H/128, S/128), 256 threads.
// ---------------------------------------------------------------------------
#define KT    32
#define PITCH 40

__global__ __launch_bounds__(256) void gemm_mma_kernel(
    const __nv_bfloat16* __restrict__ Ah, const __nv_bfloat16* __restrict__ Al,
    const __nv_bfloat16* __restrict__ Bh, const __nv_bfloat16* __restrict__ Bl,
    const float* __restrict__ bias, float* __restrict__ C)
{
    __shared__ __align__(16) __nv_bfloat16 sm[4][128 * PITCH];  // Ah, Al, Bh, Bl

    const int tid  = threadIdx.x;
    const int lane = tid & 31;
    const int wid  = tid >> 5;
    const int wm   = wid & 1;        // 0..1  (M)
    const int wn   = wid >> 1;       // 0..3  (N)
    const int bx   = blockIdx.x;     // N tile
    const int by   = blockIdx.y;     // M tile

    const __nv_bfloat16* srcs[4] = { Ah, Al, Bh, Bl };
    const int rb[4] = { by * 128, by * 128, bx * 128, bx * 128 };

    float acc[4][4][4];
    #pragma unroll
    for (int i = 0; i < 4; i++)
        #pragma unroll
        for (int j = 0; j < 4; j++)
            #pragma unroll
            for (int c = 0; c < 4; c++) acc[i][j][c] = 0.0f;

    // per-thread smem byte offsets for ldmatrix (A-style and B-style)
    const uint32_t a_row = wm * 64 + (lane & 15);          // + mt*16
    const uint32_t a_koff = ((lane >> 4) << 3);            // 0 or 8 (bf16)
    const uint32_t b_row = wn * 32 + ((lane >> 3) & 1) * 8 + (lane & 7);  // + nt2*16
    const uint32_t b_koff = ((lane >> 4) << 3);

    const uint32_t smb[4] = { smem_u32(&sm[0][0]), smem_u32(&sm[1][0]),
                              smem_u32(&sm[2][0]), smem_u32(&sm[3][0]) };

    for (int kt = 0; kt < KDIM / KT; kt++) {
        __syncthreads();   // previous iteration's readers done
        // load 4 tiles: 128 rows x 32 bf16 (4 x 16B chunks per row)
        #pragma unroll
        for (int arr = 0; arr < 4; arr++) {
            const __nv_bfloat16* gb = srcs[arr] + (size_t)rb[arr] * KDIM + kt * KT;
            #pragma unroll
            for (int it = 0; it < 2; it++) {
                int f   = tid + it * 256;        // 0..511
                int row = f >> 2;
                int c   = f & 3;                 // 16B chunk
                float4 v = *(const float4*)(gb + (size_t)row * KDIM + c * 8);
                *(float4*)(&sm[arr][row * PITCH + c * 8]) = v;
            }
        }
        __syncthreads();

        #pragma unroll
        for (int kk = 0; kk < 2; kk++) {
            const uint32_t k0 = kk * 16;

            // A fragments (hi & lo): 4 m-tiles each
            uint32_t ah[4][4], al[4][4];
            #pragma unroll
            for (int mt = 0; mt < 4; mt++) {
                uint32_t off = ((a_row + mt * 16) * PITCH + k0 + a_koff) * 2;
                ldsm_x4(ah[mt], smb[0] + off);
                ldsm_x4(al[mt], smb[1] + off);
            }
            // B fragments (hi & lo): 2 n16-groups; x4 = {b0_n0, b0_n8, b1_n0, b1_n8}
            uint32_t bh[2][4], bl[2][4];
            #pragma unroll
            for (int nt2 = 0; nt2 < 2; nt2++) {
                uint32_t off = ((b_row + nt2 * 16) * PITCH + k0 + b_koff) * 2;
                ldsm_x4(bh[nt2], smb[2] + off);
                ldsm_x4(bl[nt2], smb[3] + off);
            }

            #pragma unroll
            for (int mt = 0; mt < 4; mt++)
                #pragma unroll
                for (int nt = 0; nt < 4; nt++) {
                    const int g = nt >> 1, h = nt & 1;
                    mma_bf16(acc[mt][nt], ah[mt], bh[g][h], bh[g][h + 2]);
                    mma_bf16(acc[mt][nt], ah[mt], bl[g][h], bl[g][h + 2]);
                    mma_bf16(acc[mt][nt], al[mt], bh[g][h], bh[g][h + 2]);
                }
        }
    }

    // epilogue: acc[mt][nt]: c0,c1 -> row m0+lane/4, cols n0+(lane%4)*2 (+1);
    //           c2,c3 -> row +8
    const int m0 = by * 128 + wm * 64 + (lane >> 2);
    const int n0 = bx * 128 + wn * 32 + (lane & 3) * 2;
    #pragma unroll
    for (int mt = 0; mt < 4; mt++) {
        #pragma unroll
        for (int nt = 0; nt < 4; nt++) {
            const int col = n0 + nt * 8;
            const float b0 = bias[col], b1 = bias[col + 1];
            float* p0 = C + (size_t)(m0 + mt * 16) * H + col;
            float* p1 = C + (size_t)(m0 + mt * 16 + 8) * H + col;
            float2 v0 = make_float2(acc[mt][nt][0] + b0, acc[mt][nt][1] + b1);
            float2 v1 = make_float2(acc[mt][nt][2] + b0, acc[mt][nt][3] + b1);
            *(float2*)p0 = v0;
            *(float2*)p1 = v1;
        }
    }
}

// ---------------------------------------------------------------------------
// Block-sparse flash attention (unchanged from R7 — conflict-free LDS layout)
// ---------------------------------------------------------------------------
#define ATTN_SMEM ((64 * 17 + 64 * 17 + 64 * 16) * 16)

__global__ __launch_bounds__(256) void sparse_attn_kernel(
    const float* __restrict__ Q, const float* __restrict__ K,
    const float* __restrict__ V, float* __restrict__ Out)
{
    extern __shared__ float4 dsm[];
    float4* Qs = dsm;
    float4* Ks = dsm + 64 * 17;
    float4* Vs = dsm + 2 * 64 * 17;

    const int qb   = blockIdx.x;
    const int head = blockIdx.y;
    const int tid  = threadIdx.x;
    const int r    = tid >> 2;
    const int q    = tid & 3;

    const float SCALE = 0.125f * 1.44269504088896340736f;

    {
        const float* Qbase = Q + (size_t)(qb * BS) * H + head * HD;
        #pragma unroll
        for (int it = 0; it < 4; it++) {
            int f   = tid + 256 * it;
            int row = f >> 4;
            int c4  = f & 15;
            float4 v = *(const float4*)(Qbase + (size_t)row * H + c4 * 4);
            v.x *= SCALE; v.y *= SCALE; v.z *= SCALE; v.w *= SCALE;
            Qs[row * 17 + c4] = v;
        }
    }

    float O[16];
    #pragma unroll
    for (int i = 0; i < 16; i++) O[i] = 0.0f;
    float m = -INFINITY;
    float l = 0.0f;

    const int cnt = g_cnt[qb];

    for (int jj = 0; jj < cnt; jj++) {
        const int kr0 = g_cols[qb][jj] * BS;

        __syncthreads();
        {
            const float* Kb = K + (size_t)kr0 * H + head * HD;
            const float* Vb = V + (size_t)kr0 * H + head * HD;
            #pragma unroll
            for (int it = 0; it < 4; it++) {
                int f   = tid + 256 * it;
                int row = f >> 4;
                int c4  = f & 15;
                Ks[row * 17 + c4] = *(const float4*)(Kb + (size_t)row * H + c4 * 4);
                Vs[row * 16 + c4] = *(const float4*)(Vb + (size_t)row * H + c4 * 4);
            }
        }
        __syncthreads();

        float s[16];
        #pragma unroll
        for (int i = 0; i < 16; i++) s[i] = 0.0f;
        #pragma unroll
        for (int d4 = 0; d4 < 16; d4++) {
            float4 qv = Qs[r * 17 + d4];
            #pragma unroll
            for (int i = 0; i < 16; i++) {
                float4 kv = Ks[(4 * i + q) * 17 + d4];
                s[i] = fmaf(qv.x, kv.x, s[i]);
                s[i] = fmaf(qv.y, kv.y, s[i]);
                s[i] = fmaf(qv.z, kv.z, s[i]);
                s[i] = fmaf(qv.w, kv.w, s[i]);
            }
        }

        float smax = s[0];
        #pragma unroll
        for (int i = 1; i < 16; i++) smax = fmaxf(smax, s[i]);
        smax = fmaxf(smax, __shfl_xor_sync(0xffffffffu, smax, 1));
        smax = fmaxf(smax, __shfl_xor_sync(0xffffffffu, smax, 2));
        float mnew  = fmaxf(m, smax);
        float alpha = exp2f(m - mnew);

        float lsum = 0.0f;
        #pragma unroll
        for (int i = 0; i < 16; i++) {
            s[i] = exp2f(s[i] - mnew);
            lsum += s[i];
        }
        lsum += __shfl_xor_sync(0xffffffffu, lsum, 1);
        lsum += __shfl_xor_sync(0xffffffffu, lsum, 2);
        l = l * alpha + lsum;
        m = mnew;
        #pragma unroll
        for (int i = 0; i < 16; i++) O[i] *= alpha;

        #pragma unroll
        for (int i = 0; i < 16; i++) {
            #pragma unroll
            for (int qq = 0; qq < 4; qq++) {
                float pc = __shfl_sync(0xffffffffu, s[i], qq, 4);
                const int c = 4 * i + qq;
                #pragma unroll
                for (int i4 = 0; i4 < 4; i4++) {
                    float4 vv = Vs[c * 16 + 4 * i4 + q];
                    O[i4 * 4 + 0] = fmaf(pc, vv.x, O[i4 * 4 + 0]);
                    O[i4 * 4 + 1] = fmaf(pc, vv.y, O[i4 * 4 + 1]);
                    O[i4 * 4 + 2] = fmaf(pc, vv.z, O[i4 * 4 + 2]);
                    O[i4 * 4 + 3] = fmaf(pc, vv.w, O[i4 * 4 + 3]);
                }
            }
        }
    }

    const float inv = 1.0f / l;
    float* outp = Out + (size_t)(qb * BS + r) * H + head * HD;
    #pragma unroll
    for (int i4 = 0; i4 < 4; i4++) {
        float4 o = make_float4(O[i4 * 4 + 0] * inv, O[i4 * 4 + 1] * inv,
                               O[i4 * 4 + 2] * inv, O[i4 * 4 + 3] * inv);
        *(float4*)(outp + (4 * i4 + q) * 4) = o;
    }
}

// ---------------------------------------------------------------------------
// Launch
// Inputs (metadata order): hidden_states, wq, bq, wk, bk, wv, bv, wo, bo, mask
// ---------------------------------------------------------------------------
extern "C" void kernel_launch(void* const* d_in, const int* in_sizes, int n_in,
                              void* d_out, int out_size)
{
    const float* x    = (const float*)d_in[0];
    const float* wq   = (const float*)d_in[1];
    const float* bq   = (const float*)d_in[2];
    const float* wk   = (const float*)d_in[3];
    const float* bk   = (const float*)d_in[4];
    const float* wv   = (const float*)d_in[5];
    const float* bv   = (const float*)d_in[6];
    const float* wo   = (const float*)d_in[7];
    const float* bo   = (const float*)d_in[8];
    const void*  mask = (const void*)d_in[9];
    float* out = (float*)d_out;

    float *dq, *dk, *dv, *dattn;
    cudaGetSymbolAddress((void**)&dq, g_q);
    cudaGetSymbolAddress((void**)&dk, g_k);
    cudaGetSymbolAddress((void**)&dv, g_v);
    cudaGetSymbolAddress((void**)&dattn, g_attn);
    __nv_bfloat16 *xh, *xl, *ah, *al;
    __nv_bfloat16 *wqh, *wql, *wkh, *wkl, *wvh, *wvl, *woh, *wol;
    cudaGetSymbolAddress((void**)&xh, g_xh);
    cudaGetSymbolAddress((void**)&xl, g_xl);
    cudaGetSymbolAddress((void**)&ah, g_ah);
    cudaGetSymbolAddress((void**)&al, g_al);
    cudaGetSymbolAddress((void**)&wqh, g_wqh);
    cudaGetSymbolAddress((void**)&wql, g_wql);
    cudaGetSymbolAddress((void**)&wkh, g_wkh);
    cudaGetSymbolAddress((void**)&wkl, g_wkl);
    cudaGetSymbolAddress((void**)&wvh, g_wvh);
    cudaGetSymbolAddress((void**)&wvl, g_wvl);
    cudaGetSymbolAddress((void**)&woh, g_woh);
    cudaGetSymbolAddress((void**)&wol, g_wol);

    cudaFuncSetAttribute(sparse_attn_kernel,
                         cudaFuncAttributeMaxDynamicSharedMemorySize, ATTN_SMEM);

    build_blockmask_kernel<<<1, 64>>>(mask);

    const int nx4 = S * H / 4;
    const int nw4 = H * H / 4;
    split_bf16_kernel<<<nx4 / 256, 256>>>(x,  xh,  xl,  nx4);
    split_bf16_kernel<<<nw4 / 256, 256>>>(wq, wqh, wql, nw4);
    split_bf16_kernel<<<nw4 / 256, 256>>>(wk, wkh, wkl, nw4);
    split_bf16_kernel<<<nw4 / 256, 256>>>(wv, wvh, wvl, nw4);
    split_bf16_kernel<<<nw4 / 256, 256>>>(wo, woh, wol, nw4);

    dim3 gemmGrid(H / 128, S / 128);   // (8, 32)
    gemm_mma_kernel<<<gemmGrid, 256>>>(xh, xl, wqh, wql, bq, dq);
    gemm_mma_kernel<<<gemmGrid, 256>>>(xh, xl, wkh, wkl, bk, dk);
    gemm_mma_kernel<<<gemmGrid, 256>>>(xh, xl, wvh, wvl, bv, dv);

    dim3 attnGrid(NB, NH);
    sparse_attn_kernel<<<attnGrid, 256, ATTN_SMEM>>>(dq, dk, dv, dattn);

    split_bf16_kernel<<<nx4 / 256, 256>>>(dattn, ah, al, nx4);
    gemm_mma_kernel<<<gemmGrid, 256>>>(ah, al, woh, wol, bo, out);
}

// round 11
// speedup vs baseline: 2.3375x; 1.5025x over previous
#include <cuda_runtime.h>
#include <cuda_bf16.h>
#include <cstdint>
#include <math.h>

// Problem constants
#define S    4096
#define H    1024
#define NH   16
#define HD   64
#define BS   64
#define NB   (S / BS)
#define KDIM 1024

// ---------------------------------------------------------------------------
// Scratch (device globals; no allocation allowed)
// ---------------------------------------------------------------------------
__device__ float g_q[S * H];
__device__ float g_k[S * H];
__device__ float g_v[S * H];
__device__ float g_attn[S * H];
__device__ unsigned char g_cols[NB][NB];
__device__ int g_cnt[NB];

// bf16 split operands (hi/lo)
__device__ __align__(16) __nv_bfloat16 g_xh[S * H];
__device__ __align__(16) __nv_bfloat16 g_xl[S * H];
__device__ __align__(16) __nv_bfloat16 g_ah[S * H];
__device__ __align__(16) __nv_bfloat16 g_al[S * H];
__device__ __align__(16) __nv_bfloat16 g_wqh[H * H];
__device__ __align__(16) __nv_bfloat16 g_wql[H * H];
__device__ __align__(16) __nv_bfloat16 g_wkh[H * H];
__device__ __align__(16) __nv_bfloat16 g_wkl[H * H];
__device__ __align__(16) __nv_bfloat16 g_wvh[H * H];
__device__ __align__(16) __nv_bfloat16 g_wvl[H * H];
__device__ __align__(16) __nv_bfloat16 g_woh[H * H];
__device__ __align__(16) __nv_bfloat16 g_wol[H * H];

// ---------------------------------------------------------------------------
// Baseline-PTX primitives (sm_80+ ISA, compiles at compute_103)
// ---------------------------------------------------------------------------
__device__ __forceinline__ uint32_t smem_u32(const void* p) {
    uint32_t a;
    asm("{ .reg .u64 t; cvta.to.shared.u64 t, %1; cvt.u32.u64 %0, t; }"
        : "=r"(a) : "l"(p));
    return a;
}
__device__ __forceinline__ void ldsm_x4(uint32_t* r, uint32_t addr) {
    asm volatile("ldmatrix.sync.aligned.m8n8.x4.shared.b16 {%0,%1,%2,%3}, [%4];"
                 : "=r"(r[0]), "=r"(r[1]), "=r"(r[2]), "=r"(r[3]) : "r"(addr));
}
__device__ __forceinline__ void mma_bf16(float* d, const uint32_t* a,
                                         uint32_t b0, uint32_t b1) {
    asm volatile(
        "mma.sync.aligned.m16n8k16.row.col.f32.bf16.bf16.f32 "
        "{%0,%1,%2,%3}, {%4,%5,%6,%7}, {%8,%9}, {%0,%1,%2,%3};"
        : "+f"(d[0]), "+f"(d[1]), "+f"(d[2]), "+f"(d[3])
        : "r"(a[0]), "r"(a[1]), "r"(a[2]), "r"(a[3]), "r"(b0), "r"(b1));
}
__device__ __forceinline__ void cp_async16(uint32_t dst, const void* src) {
    asm volatile("cp.async.cg.shared.global [%0], [%1], 16;"
                 :: "r"(dst), "l"(src) : "memory");
}
#define CP_COMMIT() asm volatile("cp.async.commit_group;" ::: "memory")
#define CP_WAIT(n)  asm volatile("cp.async.wait_group %0;" :: "n"(n) : "memory")

// ---------------------------------------------------------------------------
// Block mask -> per-qblock active column lists
// ---------------------------------------------------------------------------
__global__ void build_blockmask_kernel(const void* __restrict__ mask) {
    int i = threadIdx.x;
    if (i >= NB) return;
    unsigned int w0 = *(const unsigned int*)mask;
    int mode;
    if (w0 == 0x3F800000u)      mode = 0;
    else if (w0 == 0x01010101u) mode = 1;
    else if (w0 == 0x3F803F80u) mode = 2;
    else                        mode = 3;

    int cnt = 0;
    for (int j = 0; j < NB; j++) {
        size_t idx = (size_t)(i * BS) * S + (size_t)(j * BS);
        bool on;
        if (mode == 0)      on = ((const float*)mask)[idx] != 0.0f;
        else if (mode == 1) on = ((const unsigned char*)mask)[idx] != 0;
        else if (mode == 2) on = __bfloat162float(((const __nv_bfloat16*)mask)[idx]) != 0.0f;
        else                on = ((const int*)mask)[idx] != 0;
        if (on) g_cols[i][cnt++] = (unsigned char)j;
    }
    g_cnt[i] = cnt;
}

// ---------------------------------------------------------------------------
// fp32 -> bf16 hi/lo split.  x = hi + lo + O(2^-17 x).
// ---------------------------------------------------------------------------
__global__ __launch_bounds__(256) void split_bf16_kernel(
    const float* __restrict__ src,
    __nv_bfloat16* __restrict__ hi, __nv_bfloat16* __restrict__ lo, int n4)
{
    int i = blockIdx.x * 256 + threadIdx.x;
    if (i >= n4) return;
    float4 v = ((const float4*)src)[i];
    __nv_bfloat16 h0 = __float2bfloat16(v.x);
    __nv_bfloat16 h1 = __float2bfloat16(v.y);
    __nv_bfloat16 h2 = __float2bfloat16(v.z);
    __nv_bfloat16 h3 = __float2bfloat16(v.w);
    __nv_bfloat16 l0 = __float2bfloat16(v.x - __bfloat162float(h0));
    __nv_bfloat16 l1 = __float2bfloat16(v.y - __bfloat162float(h1));
    __nv_bfloat16 l2 = __float2bfloat16(v.z - __bfloat162float(h2));
    __nv_bfloat16 l3 = __float2bfloat16(v.w - __bfloat162float(h3));
    __nv_bfloat162* hp = (__nv_bfloat162*)hi;
    __nv_bfloat162* lp = (__nv_bfloat162*)lo;
    hp[2 * i + 0] = __nv_bfloat162(h0, h1);
    hp[2 * i + 1] = __nv_bfloat162(h2, h3);
    lp[2 * i + 0] = __nv_bfloat162(l0, l1);
    lp[2 * i + 1] = __nv_bfloat162(l2, l3);
}

// ---------------------------------------------------------------------------
// mma.sync bf16-split GEMM with 3-stage cp.async pipeline.
// C[M,N] = A @ B^T + bias, fp32-accurate via Ah@Bh + Ah@Bl + Al@Bh.
// CTA 128x128, 8 warps (2 M x 4 N), warp tile 64x32, k-tile 32.
// Smem pitch 40 bf16 (80B rows): ldmatrix addresses conflict-free.
// One __syncthreads per k-tile; cp.async keeps 2 stages in flight.
// Grid: (H/128, S/128), 256 threads, 120 KB dynamic smem.
// ---------------------------------------------------------------------------
#define KT      32
#define PITCH   40
#define NKT     (KDIM / KT)                 // 32
#define TILEB   (128 * PITCH * 2)           // 10240 B per tile
#define STAGEB  (4 * TILEB)                 // 40960 B per stage
#define GEMM_SMEM (3 * STAGEB)              // 122880 B

__global__ __launch_bounds__(256) void gemm_mma_kernel(
    const __nv_bfloat16* __restrict__ Ah, const __nv_bfloat16* __restrict__ Al,
    const __nv_bfloat16* __restrict__ Bh, const __nv_bfloat16* __restrict__ Bl,
    const float* __restrict__ bias, float* __restrict__ C)
{
    extern __shared__ __align__(16) char gsm[];
    const uint32_t smem0 = smem_u32(gsm);

    const int tid  = threadIdx.x;
    const int lane = tid & 31;
    const int wid  = tid >> 5;
    const int wm   = wid & 1;        // 0..1  (M)
    const int wn   = wid >> 1;       // 0..3  (N)
    const int bx   = blockIdx.x;     // N tile
    const int by   = blockIdx.y;     // M tile

    const __nv_bfloat16* srcs[4] = { Ah, Al, Bh, Bl };
    const int rb[4] = { by * 128, by * 128, bx * 128, bx * 128 };

    float acc[4][4][4];
    #pragma unroll
    for (int i = 0; i < 4; i++)
        #pragma unroll
        for (int j = 0; j < 4; j++)
            #pragma unroll
            for (int c = 0; c < 4; c++) acc[i][j][c] = 0.0f;

    // per-thread load mapping: row = f>>2 (0..127), 16B chunk = f&3
    const int ldrow = tid >> 2;            // rows tid/4 and tid/4+64
    const int ldc   = tid & 3;

    // per-thread ldmatrix offsets
    const uint32_t a_row  = wm * 64 + (lane & 15);
    const uint32_t a_koff = ((lane >> 4) << 3);
    const uint32_t b_row  = wn * 32 + ((lane >> 3) & 1) * 8 + (lane & 7);
    const uint32_t b_koff = ((lane >> 4) << 3);

    auto load_stage = [&](int kt, int st) {
        const uint32_t sbase = smem0 + st * STAGEB;
        #pragma unroll
        for (int arr = 0; arr < 4; arr++) {
            const __nv_bfloat16* gb = srcs[arr] + (size_t)rb[arr] * KDIM + kt * KT;
            const uint32_t abase = sbase + arr * TILEB;
            #pragma unroll
            for (int it = 0; it < 2; it++) {
                int row = ldrow + it * 64;
                cp_async16(abase + (row * PITCH + ldc * 8) * 2,
                           gb + (size_t)row * KDIM + ldc * 8);
            }
        }
    };

    load_stage(0, 0); CP_COMMIT();
    load_stage(1, 1); CP_COMMIT();

    for (int kt = 0; kt < NKT; kt++) {
        if (kt == NKT - 1) { CP_WAIT(0); } else { CP_WAIT(1); }
        __syncthreads();   // stage kt ready; everyone done with stage (kt-1)%3

        if (kt + 2 < NKT) { load_stage(kt + 2, (kt + 2) % 3); CP_COMMIT(); }

        const uint32_t sb = smem0 + (kt % 3) * STAGEB;
        const uint32_t sA_h = sb + 0 * TILEB;
        const uint32_t sA_l = sb + 1 * TILEB;
        const uint32_t sB_h = sb + 2 * TILEB;
        const uint32_t sB_l = sb + 3 * TILEB;

        #pragma unroll
        for (int kk = 0; kk < 2; kk++) {
            const uint32_t k0 = kk * 16;

            uint32_t ah[4][4], al[4][4];
            #pragma unroll
            for (int mt = 0; mt < 4; mt++) {
                uint32_t off = ((a_row + mt * 16) * PITCH + k0 + a_koff) * 2;
                ldsm_x4(ah[mt], sA_h + off);
                ldsm_x4(al[mt], sA_l + off);
            }
            uint32_t bh[2][4], bl[2][4];
            #pragma unroll
            for (int nt2 = 0; nt2 < 2; nt2++) {
                uint32_t off = ((b_row + nt2 * 16) * PITCH + k0 + b_koff) * 2;
                ldsm_x4(bh[nt2], sB_h + off);
                ldsm_x4(bl[nt2], sB_l + off);
            }

            #pragma unroll
            for (int mt = 0; mt < 4; mt++)
                #pragma unroll
                for (int nt = 0; nt < 4; nt++) {
                    const int g = nt >> 1, h = nt & 1;
                    mma_bf16(acc[mt][nt], ah[mt], bh[g][h], bh[g][h + 2]);
                    mma_bf16(acc[mt][nt], ah[mt], bl[g][h], bl[g][h + 2]);
                    mma_bf16(acc[mt][nt], al[mt], bh[g][h], bh[g][h + 2]);
                }
        }
    }

    // epilogue
    const int m0 = by * 128 + wm * 64 + (lane >> 2);
    const int n0 = bx * 128 + wn * 32 + (lane & 3) * 2;
    #pragma unroll
    for (int mt = 0; mt < 4; mt++) {
        #pragma unroll
        for (int nt = 0; nt < 4; nt++) {
            const int col = n0 + nt * 8;
            const float b0 = bias[col], b1 = bias[col + 1];
            float* p0 = C + (size_t)(m0 + mt * 16) * H + col;
            float* p1 = C + (size_t)(m0 + mt * 16 + 8) * H + col;
            *(float2*)p0 = make_float2(acc[mt][nt][0] + b0, acc[mt][nt][1] + b1);
            *(float2*)p1 = make_float2(acc[mt][nt][2] + b0, acc[mt][nt][3] + b1);
        }
    }
}

// ---------------------------------------------------------------------------
// Block-sparse flash attention (unchanged — conflict-free LDS layout)
// ---------------------------------------------------------------------------
#define ATTN_SMEM ((64 * 17 + 64 * 17 + 64 * 16) * 16)

__global__ __launch_bounds__(256) void sparse_attn_kernel(
    const float* __restrict__ Q, const float* __restrict__ K,
    const float* __restrict__ V, float* __restrict__ Out)
{
    extern __shared__ float4 dsm[];
    float4* Qs = dsm;
    float4* Ks = dsm + 64 * 17;
    float4* Vs = dsm + 2 * 64 * 17;

    const int qb   = blockIdx.x;
    const int head = blockIdx.y;
    const int tid  = threadIdx.x;
    const int r    = tid >> 2;
    const int q    = tid & 3;

    const float SCALE = 0.125f * 1.44269504088896340736f;

    {
        const float* Qbase = Q + (size_t)(qb * BS) * H + head * HD;
        #pragma unroll
        for (int it = 0; it < 4; it++) {
            int f   = tid + 256 * it;
            int row = f >> 4;
            int c4  = f & 15;
            float4 v = *(const float4*)(Qbase + (size_t)row * H + c4 * 4);
            v.x *= SCALE; v.y *= SCALE; v.z *= SCALE; v.w *= SCALE;
            Qs[row * 17 + c4] = v;
        }
    }

    float O[16];
    #pragma unroll
    for (int i = 0; i < 16; i++) O[i] = 0.0f;
    float m = -INFINITY;
    float l = 0.0f;

    const int cnt = g_cnt[qb];

    for (int jj = 0; jj < cnt; jj++) {
        const int kr0 = g_cols[qb][jj] * BS;

        __syncthreads();
        {
            const float* Kb = K + (size_t)kr0 * H + head * HD;
            const float* Vb = V + (size_t)kr0 * H + head * HD;
            #pragma unroll
            for (int it = 0; it < 4; it++) {
                int f   = tid + 256 * it;
                int row = f >> 4;
                int c4  = f & 15;
                Ks[row * 17 + c4] = *(const float4*)(Kb + (size_t)row * H + c4 * 4);
                Vs[row * 16 + c4] = *(const float4*)(Vb + (size_t)row * H + c4 * 4);
            }
        }
        __syncthreads();

        float s[16];
        #pragma unroll
        for (int i = 0; i < 16; i++) s[i] = 0.0f;
        #pragma unroll
        for (int d4 = 0; d4 < 16; d4++) {
            float4 qv = Qs[r * 17 + d4];
            #pragma unroll
            for (int i = 0; i < 16; i++) {
                float4 kv = Ks[(4 * i + q) * 17 + d4];
                s[i] = fmaf(qv.x, kv.x, s[i]);
                s[i] = fmaf(qv.y, kv.y, s[i]);
                s[i] = fmaf(qv.z, kv.z, s[i]);
                s[i] = fmaf(qv.w, kv.w, s[i]);
            }
        }

        float smax = s[0];
        #pragma unroll
        for (int i = 1; i < 16; i++) smax = fmaxf(smax, s[i]);
        smax = fmaxf(smax, __shfl_xor_sync(0xffffffffu, smax, 1));
        smax = fmaxf(smax, __shfl_xor_sync(0xffffffffu, smax, 2));
        float mnew  = fmaxf(m, smax);
        float alpha = exp2f(m - mnew);

        float lsum = 0.0f;
        #pragma unroll
        for (int i = 0; i < 16; i++) {
            s[i] = exp2f(s[i] - mnew);
            lsum += s[i];
        }
        lsum += __shfl_xor_sync(0xffffffffu, lsum, 1);
        lsum += __shfl_xor_sync(0xffffffffu, lsum, 2);
        l = l * alpha + lsum;
        m = mnew;
        #pragma unroll
        for (int i = 0; i < 16; i++) O[i] *= alpha;

        #pragma unroll
        for (int i = 0; i < 16; i++) {
            #pragma unroll
            for (int qq = 0; qq < 4; qq++) {
                float pc = __shfl_sync(0xffffffffu, s[i], qq, 4);
                const int c = 4 * i + qq;
                #pragma unroll
                for (int i4 = 0; i4 < 4; i4++) {
                    float4 vv = Vs[c * 16 + 4 * i4 + q];
                    O[i4 * 4 + 0] = fmaf(pc, vv.x, O[i4 * 4 + 0]);
                    O[i4 * 4 + 1] = fmaf(pc, vv.y, O[i4 * 4 + 1]);
                    O[i4 * 4 + 2] = fmaf(pc, vv.z, O[i4 * 4 + 2]);
                    O[i4 * 4 + 3] = fmaf(pc, vv.w, O[i4 * 4 + 3]);
                }
            }
        }
    }

    const float inv = 1.0f / l;
    float* outp = Out + (size_t)(qb * BS + r) * H + head * HD;
    #pragma unroll
    for (int i4 = 0; i4 < 4; i4++) {
        float4 o = make_float4(O[i4 * 4 + 0] * inv, O[i4 * 4 + 1] * inv,
                               O[i4 * 4 + 2] * inv, O[i4 * 4 + 3] * inv);
        *(float4*)(outp + (4 * i4 + q) * 4) = o;
    }
}

// ---------------------------------------------------------------------------
// Launch
// Inputs (metadata order): hidden_states, wq, bq, wk, bk, wv, bv, wo, bo, mask
// ---------------------------------------------------------------------------
extern "C" void kernel_launch(void* const* d_in, const int* in_sizes, int n_in,
                              void* d_out, int out_size)
{
    const float* x    = (const float*)d_in[0];
    const float* wq   = (const float*)d_in[1];
    const float* bq   = (const float*)d_in[2];
    const float* wk   = (const float*)d_in[3];
    const float* bk   = (const float*)d_in[4];
    const float* wv   = (const float*)d_in[5];
    const float* bv   = (const float*)d_in[6];
    const float* wo   = (const float*)d_in[7];
    const float* bo   = (const float*)d_in[8];
    const void*  mask = (const void*)d_in[9];
    float* out = (float*)d_out;

    float *dq, *dk, *dv, *dattn;
    cudaGetSymbolAddress((void**)&dq, g_q);
    cudaGetSymbolAddress((void**)&dk, g_k);
    cudaGetSymbolAddress((void**)&dv, g_v);
    cudaGetSymbolAddress((void**)&dattn, g_attn);
    __nv_bfloat16 *xh, *xl, *ah, *al;
    __nv_bfloat16 *wqh, *wql, *wkh, *wkl, *wvh, *wvl, *woh, *wol;
    cudaGetSymbolAddress((void**)&xh, g_xh);
    cudaGetSymbolAddress((void**)&xl, g_xl);
    cudaGetSymbolAddress((void**)&ah, g_ah);
    cudaGetSymbolAddress((void**)&al, g_al);
    cudaGetSymbolAddress((void**)&wqh, g_wqh);
    cudaGetSymbolAddress((void**)&wql, g_wql);
    cudaGetSymbolAddress((void**)&wkh, g_wkh);
    cudaGetSymbolAddress((void**)&wkl, g_wkl);
    cudaGetSymbolAddress((void**)&wvh, g_wvh);
    cudaGetSymbolAddress((void**)&wvl, g_wvl);
    cudaGetSymbolAddress((void**)&woh, g_woh);
    cudaGetSymbolAddress((void**)&wol, g_wol);

    cudaFuncSetAttribute(sparse_attn_kernel,
                         cudaFuncAttributeMaxDynamicSharedMemorySize, ATTN_SMEM);
    cudaFuncSetAttribute(gemm_mma_kernel,
                         cudaFuncAttributeMaxDynamicSharedMemorySize, GEMM_SMEM);

    build_blockmask_kernel<<<1, 64>>>(mask);

    const int nx4 = S * H / 4;
    const int nw4 = H * H / 4;
    split_bf16_kernel<<<nx4 / 256, 256>>>(x,  xh,  xl,  nx4);
    split_bf16_kernel<<<nw4 / 256, 256>>>(wq, wqh, wql, nw4);
    split_bf16_kernel<<<nw4 / 256, 256>>>(wk, wkh, wkl, nw4);
    split_bf16_kernel<<<nw4 / 256, 256>>>(wv, wvh, wvl, nw4);
    split_bf16_kernel<<<nw4 / 256, 256>>>(wo, woh, wol, nw4);

    dim3 gemmGrid(H / 128, S / 128);   // (8, 32)
    gemm_mma_kernel<<<gemmGrid, 256, GEMM_SMEM>>>(xh, xl, wqh, wql, bq, dq);
    gemm_mma_kernel<<<gemmGrid, 256, GEMM_SMEM>>>(xh, xl, wkh, wkl, bk, dk);
    gemm_mma_kernel<<<gemmGrid, 256, GEMM_SMEM>>>(xh, xl, wvh, wvl, bv, dv);

    dim3 attnGrid(NB, NH);
    sparse_attn_kernel<<<attnGrid, 256, ATTN_SMEM>>>(dq, dk, dv, dattn);

    split_bf16_kernel<<<nx4 / 256, 256>>>(dattn, ah, al, nx4);
    gemm_mma_kernel<<<gemmGrid, 256, GEMM_SMEM>>>(ah, al, woh, wol, bo, out);
}

// round 12
// speedup vs baseline: 3.5359x; 1.5127x over previous
#include <cuda_runtime.h>
#include <cuda_bf16.h>
#include <cstdint>
#include <math.h>

// Problem constants
#define S    4096
#define H    1024
#define NH   16
#define HD   64
#define BS   64
#define NB   (S / BS)
#define KDIM 1024

// ---------------------------------------------------------------------------
// Scratch (device globals; no allocation allowed)
// ---------------------------------------------------------------------------
__device__ float g_q[S * H];
__device__ float g_k[S * H];
__device__ float g_v[S * H];
__device__ float g_attn[S * H];
__device__ unsigned char g_cols[NB][NB];
__device__ int g_cnt[NB];

// bf16 split operands (hi/lo)
__device__ __align__(16) __nv_bfloat16 g_xh[S * H];
__device__ __align__(16) __nv_bfloat16 g_xl[S * H];
__device__ __align__(16) __nv_bfloat16 g_ah[S * H];
__device__ __align__(16) __nv_bfloat16 g_al[S * H];
__device__ __align__(16) __nv_bfloat16 g_wqh[H * H];
__device__ __align__(16) __nv_bfloat16 g_wql[H * H];
__device__ __align__(16) __nv_bfloat16 g_wkh[H * H];
__device__ __align__(16) __nv_bfloat16 g_wkl[H * H];
__device__ __align__(16) __nv_bfloat16 g_wvh[H * H];
__device__ __align__(16) __nv_bfloat16 g_wvl[H * H];
__device__ __align__(16) __nv_bfloat16 g_woh[H * H];
__device__ __align__(16) __nv_bfloat16 g_wol[H * H];
// QKV splits for mma attention
__device__ __align__(16) __nv_bfloat16 g_qsh[S * H];
__device__ __align__(16) __nv_bfloat16 g_qsl[S * H];
__device__ __align__(16) __nv_bfloat16 g_ksh[S * H];
__device__ __align__(16) __nv_bfloat16 g_ksl[S * H];
__device__ __align__(16) __nv_bfloat16 g_vsh[S * H];
__device__ __align__(16) __nv_bfloat16 g_vsl[S * H];

// ---------------------------------------------------------------------------
// Baseline-PTX primitives (sm_80+ ISA, compiles at compute_103)
// ---------------------------------------------------------------------------
__device__ __forceinline__ uint32_t smem_u32(const void* p) {
    uint32_t a;
    asm("{ .reg .u64 t; cvta.to.shared.u64 t, %1; cvt.u32.u64 %0, t; }"
        : "=r"(a) : "l"(p));
    return a;
}
__device__ __forceinline__ void ldsm_x4(uint32_t* r, uint32_t addr) {
    asm volatile("ldmatrix.sync.aligned.m8n8.x4.shared.b16 {%0,%1,%2,%3}, [%4];"
                 : "=r"(r[0]), "=r"(r[1]), "=r"(r[2]), "=r"(r[3]) : "r"(addr));
}
__device__ __forceinline__ void ldsm_x4_trans(uint32_t* r, uint32_t addr) {
    asm volatile("ldmatrix.sync.aligned.m8n8.x4.trans.shared.b16 {%0,%1,%2,%3}, [%4];"
                 : "=r"(r[0]), "=r"(r[1]), "=r"(r[2]), "=r"(r[3]) : "r"(addr));
}
__device__ __forceinline__ void mma_bf16(float* d, const uint32_t* a,
                                         uint32_t b0, uint32_t b1) {
    asm volatile(
        "mma.sync.aligned.m16n8k16.row.col.f32.bf16.bf16.f32 "
        "{%0,%1,%2,%3}, {%4,%5,%6,%7}, {%8,%9}, {%0,%1,%2,%3};"
        : "+f"(d[0]), "+f"(d[1]), "+f"(d[2]), "+f"(d[3])
        : "r"(a[0]), "r"(a[1]), "r"(a[2]), "r"(a[3]), "r"(b0), "r"(b1));
}
__device__ __forceinline__ void cp_async16(uint32_t dst, const void* src) {
    asm volatile("cp.async.cg.shared.global [%0], [%1], 16;"
                 :: "r"(dst), "l"(src) : "memory");
}
#define CP_COMMIT() asm volatile("cp.async.commit_group;" ::: "memory")
#define CP_WAIT(n)  asm volatile("cp.async.wait_group %0;" :: "n"(n) : "memory")

__device__ __forceinline__ uint32_t pack_bf16x2(float x, float y) {
    __nv_bfloat162 h = __floats2bfloat162_rn(x, y);
    return *(uint32_t*)&h;
}

// ---------------------------------------------------------------------------
// Block mask -> per-qblock active column lists
// ---------------------------------------------------------------------------
__global__ void build_blockmask_kernel(const void* __restrict__ mask) {
    int i = threadIdx.x;
    if (i >= NB) return;
    unsigned int w0 = *(const unsigned int*)mask;
    int mode;
    if (w0 == 0x3F800000u)      mode = 0;
    else if (w0 == 0x01010101u) mode = 1;
    else if (w0 == 0x3F803F80u) mode = 2;
    else                        mode = 3;

    int cnt = 0;
    for (int j = 0; j < NB; j++) {
        size_t idx = (size_t)(i * BS) * S + (size_t)(j * BS);
        bool on;
        if (mode == 0)      on = ((const float*)mask)[idx] != 0.0f;
        else if (mode == 1) on = ((const unsigned char*)mask)[idx] != 0;
        else if (mode == 2) on = __bfloat162float(((const __nv_bfloat16*)mask)[idx]) != 0.0f;
        else                on = ((const int*)mask)[idx] != 0;
        if (on) g_cols[i][cnt++] = (unsigned char)j;
    }
    g_cnt[i] = cnt;
}

// ---------------------------------------------------------------------------
// fp32 -> bf16 hi/lo split.  x = hi + lo + O(2^-17 x).
// ---------------------------------------------------------------------------
__global__ __launch_bounds__(256) void split_bf16_kernel(
    const float* __restrict__ src,
    __nv_bfloat16* __restrict__ hi, __nv_bfloat16* __restrict__ lo, int n4)
{
    int i = blockIdx.x * 256 + threadIdx.x;
    if (i >= n4) return;
    float4 v = ((const float4*)src)[i];
    __nv_bfloat16 h0 = __float2bfloat16(v.x);
    __nv_bfloat16 h1 = __float2bfloat16(v.y);
    __nv_bfloat16 h2 = __float2bfloat16(v.z);
    __nv_bfloat16 h3 = __float2bfloat16(v.w);
    __nv_bfloat16 l0 = __float2bfloat16(v.x - __bfloat162float(h0));
    __nv_bfloat16 l1 = __float2bfloat16(v.y - __bfloat162float(h1));
    __nv_bfloat16 l2 = __float2bfloat16(v.z - __bfloat162float(h2));
    __nv_bfloat16 l3 = __float2bfloat16(v.w - __bfloat162float(h3));
    __nv_bfloat162* hp = (__nv_bfloat162*)hi;
    __nv_bfloat162* lp = (__nv_bfloat162*)lo;
    hp[2 * i + 0] = __nv_bfloat162(h0, h1);
    hp[2 * i + 1] = __nv_bfloat162(h2, h3);
    lp[2 * i + 0] = __nv_bfloat162(l0, l1);
    lp[2 * i + 1] = __nv_bfloat162(l2, l3);
}

// ---------------------------------------------------------------------------
// mma.sync bf16-split GEMM with 3-stage cp.async pipeline (unchanged, passing).
// ---------------------------------------------------------------------------
#define KT      32
#define PITCH   40
#define NKT     (KDIM / KT)
#define TILEB   (128 * PITCH * 2)
#define STAGEB  (4 * TILEB)
#define GEMM_SMEM (3 * STAGEB)

__global__ __launch_bounds__(256) void gemm_mma_kernel(
    const __nv_bfloat16* __restrict__ Ah, const __nv_bfloat16* __restrict__ Al,
    const __nv_bfloat16* __restrict__ Bh, const __nv_bfloat16* __restrict__ Bl,
    const float* __restrict__ bias, float* __restrict__ C)
{
    extern __shared__ __align__(16) char gsm[];
    const uint32_t smem0 = smem_u32(gsm);

    const int tid  = threadIdx.x;
    const int lane = tid & 31;
    const int wid  = tid >> 5;
    const int wm   = wid & 1;
    const int wn   = wid >> 1;
    const int bx   = blockIdx.x;
    const int by   = blockIdx.y;

    const __nv_bfloat16* srcs[4] = { Ah, Al, Bh, Bl };
    const int rb[4] = { by * 128, by * 128, bx * 128, bx * 128 };

    float acc[4][4][4];
    #pragma unroll
    for (int i = 0; i < 4; i++)
        #pragma unroll
        for (int j = 0; j < 4; j++)
            #pragma unroll
            for (int c = 0; c < 4; c++) acc[i][j][c] = 0.0f;

    const int ldrow = tid >> 2;
    const int ldc   = tid & 3;

    const uint32_t a_row  = wm * 64 + (lane & 15);
    const uint32_t a_koff = ((lane >> 4) << 3);
    const uint32_t b_row  = wn * 32 + ((lane >> 3) & 1) * 8 + (lane & 7);
    const uint32_t b_koff = ((lane >> 4) << 3);

    auto load_stage = [&](int kt, int st) {
        const uint32_t sbase = smem0 + st * STAGEB;
        #pragma unroll
        for (int arr = 0; arr < 4; arr++) {
            const __nv_bfloat16* gb = srcs[arr] + (size_t)rb[arr] * KDIM + kt * KT;
            const uint32_t abase = sbase + arr * TILEB;
            #pragma unroll
            for (int it = 0; it < 2; it++) {
                int row = ldrow + it * 64;
                cp_async16(abase + (row * PITCH + ldc * 8) * 2,
                           gb + (size_t)row * KDIM + ldc * 8);
            }
        }
    };

    load_stage(0, 0); CP_COMMIT();
    load_stage(1, 1); CP_COMMIT();

    for (int kt = 0; kt < NKT; kt++) {
        if (kt == NKT - 1) { CP_WAIT(0); } else { CP_WAIT(1); }
        __syncthreads();

        if (kt + 2 < NKT) { load_stage(kt + 2, (kt + 2) % 3); CP_COMMIT(); }

        const uint32_t sb = smem0 + (kt % 3) * STAGEB;
        const uint32_t sA_h = sb + 0 * TILEB;
        const uint32_t sA_l = sb + 1 * TILEB;
        const uint32_t sB_h = sb + 2 * TILEB;
        const uint32_t sB_l = sb + 3 * TILEB;

        #pragma unroll
        for (int kk = 0; kk < 2; kk++) {
            const uint32_t k0 = kk * 16;

            uint32_t ah[4][4], al[4][4];
            #pragma unroll
            for (int mt = 0; mt < 4; mt++) {
                uint32_t off = ((a_row + mt * 16) * PITCH + k0 + a_koff) * 2;
                ldsm_x4(ah[mt], sA_h + off);
                ldsm_x4(al[mt], sA_l + off);
            }
            uint32_t bh[2][4], bl[2][4];
            #pragma unroll
            for (int nt2 = 0; nt2 < 2; nt2++) {
                uint32_t off = ((b_row + nt2 * 16) * PITCH + k0 + b_koff) * 2;
                ldsm_x4(bh[nt2], sB_h + off);
                ldsm_x4(bl[nt2], sB_l + off);
            }

            #pragma unroll
            for (int mt = 0; mt < 4; mt++)
                #pragma unroll
                for (int nt = 0; nt < 4; nt++) {
                    const int g = nt >> 1, h = nt & 1;
                    mma_bf16(acc[mt][nt], ah[mt], bh[g][h], bh[g][h + 2]);
                    mma_bf16(acc[mt][nt], ah[mt], bl[g][h], bl[g][h + 2]);
                    mma_bf16(acc[mt][nt], al[mt], bh[g][h], bh[g][h + 2]);
                }
        }
    }

    const int m0 = by * 128 + wm * 64 + (lane >> 2);
    const int n0 = bx * 128 + wn * 32 + (lane & 3) * 2;
    #pragma unroll
    for (int mt = 0; mt < 4; mt++) {
        #pragma unroll
        for (int nt = 0; nt < 4; nt++) {
            const int col = n0 + nt * 8;
            const float b0 = bias[col], b1 = bias[col + 1];
            float* p0 = C + (size_t)(m0 + mt * 16) * H + col;
            float* p1 = C + (size_t)(m0 + mt * 16 + 8) * H + col;
            *(float2*)p0 = make_float2(acc[mt][nt][0] + b0, acc[mt][nt][1] + b1);
            *(float2*)p1 = make_float2(acc[mt][nt][2] + b0, acc[mt][nt][3] + b1);
        }
    }
}

// ---------------------------------------------------------------------------
// Block-sparse flash attention on mma.sync (bf16 3-term split).
// Grid: (NB, NH). 128 threads = 4 warps; warp handles 16 q-rows x 64 cols.
// Q fragments loaded once from global (direct 4B LDG at fragment coords).
// K/V tiles (hi/lo) staged via 2-stage cp.async, pitch 72 bf16.
// S accumulators double as P A-fragments for PV (FA-2 register reuse).
// ---------------------------------------------------------------------------
#define APITCH   72
#define KVTILE   (64 * APITCH * 2)       // 9216 B
#define AT_SMEM  (2 * 4 * KVTILE)        // 73728 B

__global__ __launch_bounds__(128) void sparse_attn_mma_kernel(
    const __nv_bfloat16* __restrict__ Qh, const __nv_bfloat16* __restrict__ Ql,
    const __nv_bfloat16* __restrict__ Kh, const __nv_bfloat16* __restrict__ Kl,
    const __nv_bfloat16* __restrict__ Vh, const __nv_bfloat16* __restrict__ Vl,
    float* __restrict__ Out)
{
    extern __shared__ __align__(16) char asmem[];
    const uint32_t sb0 = smem_u32(asmem);

    const int qb   = blockIdx.x;
    const int head = blockIdx.y;
    const int tid  = threadIdx.x;
    const int lane = tid & 31;
    const int wid  = tid >> 5;            // 0..3 -> q-row stripe
    const int g    = lane >> 2;           // 0..7
    const int t    = lane & 3;            // 0..3

    const float SCALE = 0.125f * 1.44269504088896340736f;

    const int r0 = qb * BS + wid * 16;    // warp's first q row
    const int cb = head * HD;             // head column base

    // --- Q fragments, loaded once (A-layout coords -> direct 4B loads) ---
    uint32_t qhf[4][4], qlf[4][4];
    #pragma unroll
    for (int kk = 0; kk < 4; kk++) {
        const int c0 = cb + kk * 16 + 2 * t;
        qhf[kk][0] = *(const uint32_t*)&Qh[(size_t)(r0 + g) * H + c0];
        qhf[kk][1] = *(const uint32_t*)&Qh[(size_t)(r0 + g + 8) * H + c0];
        qhf[kk][2] = *(const uint32_t*)&Qh[(size_t)(r0 + g) * H + c0 + 8];
        qhf[kk][3] = *(const uint32_t*)&Qh[(size_t)(r0 + g + 8) * H + c0 + 8];
        qlf[kk][0] = *(const uint32_t*)&Ql[(size_t)(r0 + g) * H + c0];
        qlf[kk][1] = *(const uint32_t*)&Ql[(size_t)(r0 + g + 8) * H + c0];
        qlf[kk][2] = *(const uint32_t*)&Ql[(size_t)(r0 + g) * H + c0 + 8];
        qlf[kk][3] = *(const uint32_t*)&Ql[(size_t)(r0 + g + 8) * H + c0 + 8];
    }

    // ldmatrix per-lane offsets
    const uint32_t b_rowl = ((lane >> 3) & 1) * 8 + (lane & 7);   // K rows (tokens)
    const uint32_t b_koff = (lane >> 4) * 8;                      // K col half
    const uint32_t v_rowl = ((lane >> 3) & 1) * 8 + (lane & 7);   // V rows (tokens)
    const uint32_t v_coff = (lane >> 4) * 8;                      // V col half

    // O accumulators + softmax state
    float O[8][4];
    #pragma unroll
    for (int j = 0; j < 8; j++)
        #pragma unroll
        for (int c = 0; c < 4; c++) O[j][c] = 0.0f;
    float m1 = -INFINITY, m2 = -INFINITY, l1 = 0.0f, l2 = 0.0f;

    const int cnt = g_cnt[qb];
    const __nv_bfloat16* kvsrc[4] = { Kh, Kl, Vh, Vl };

    auto load_stage = [&](int jblk, int st) {
        const int kr0 = jblk * BS;
        const uint32_t sbase = sb0 + st * 4 * KVTILE;
        #pragma unroll
        for (int it = 0; it < 16; it++) {
            int f    = tid + it * 128;        // 0..2047
            int arr  = f >> 9;
            int row  = (f >> 3) & 63;
            int ch   = f & 7;
            cp_async16(sbase + arr * KVTILE + (row * APITCH + ch * 8) * 2,
                       kvsrc[arr] + (size_t)(kr0 + row) * H + cb + ch * 8);
        }
    };

    load_stage(g_cols[qb][0], 0); CP_COMMIT();

    for (int jj = 0; jj < cnt; jj++) {
        const int st = jj & 1;
        if (jj + 1 < cnt) { load_stage(g_cols[qb][jj + 1], st ^ 1); CP_COMMIT(); }
        if (jj + 1 < cnt) { CP_WAIT(1); } else { CP_WAIT(0); }
        __syncthreads();   // stage st ready for all warps

        const uint32_t sKh = sb0 + st * 4 * KVTILE + 0 * KVTILE;
        const uint32_t sKl = sb0 + st * 4 * KVTILE + 1 * KVTILE;
        const uint32_t sVh = sb0 + st * 4 * KVTILE + 2 * KVTILE;
        const uint32_t sVl = sb0 + st * 4 * KVTILE + 3 * KVTILE;

        // ---- S = Q @ K^T (3 terms) ----
        float sacc[8][4];
        #pragma unroll
        for (int j = 0; j < 8; j++)
            #pragma unroll
            for (int c = 0; c < 4; c++) sacc[j][c] = 0.0f;

        #pragma unroll
        for (int kk = 0; kk < 4; kk++) {
            uint32_t kh[4][4], kl[4][4];
            #pragma unroll
            for (int g4 = 0; g4 < 4; g4++) {
                uint32_t off = ((g4 * 16 + b_rowl) * APITCH + kk * 16 + b_koff) * 2;
                ldsm_x4(kh[g4], sKh + off);
                ldsm_x4(kl[g4], sKl + off);
            }
            #pragma unroll
            for (int nt = 0; nt < 8; nt++) {
                const int g4 = nt >> 1, h = nt & 1;
                mma_bf16(sacc[nt], qhf[kk], kh[g4][h], kh[g4][h + 2]);
                mma_bf16(sacc[nt], qhf[kk], kl[g4][h], kl[g4][h + 2]);
                mma_bf16(sacc[nt], qlf[kk], kh[g4][h], kh[g4][h + 2]);
            }
        }

        // ---- scale + online softmax (rows g via c0,c1 ; g+8 via c2,c3) ----
        #pragma unroll
        for (int j = 0; j < 8; j++)
            #pragma unroll
            for (int c = 0; c < 4; c++) sacc[j][c] *= SCALE;

        float mx1 = sacc[0][0], mx2 = sacc[0][2];
        #pragma unroll
        for (int j = 0; j < 8; j++) {
            mx1 = fmaxf(mx1, fmaxf(sacc[j][0], sacc[j][1]));
            mx2 = fmaxf(mx2, fmaxf(sacc[j][2], sacc[j][3]));
        }
        mx1 = fmaxf(mx1, __shfl_xor_sync(0xffffffffu, mx1, 1));
        mx1 = fmaxf(mx1, __shfl_xor_sync(0xffffffffu, mx1, 2));
        mx2 = fmaxf(mx2, __shfl_xor_sync(0xffffffffu, mx2, 1));
        mx2 = fmaxf(mx2, __shfl_xor_sync(0xffffffffu, mx2, 2));

        const float mn1 = fmaxf(m1, mx1);
        const float mn2 = fmaxf(m2, mx2);
        const float al1 = exp2f(m1 - mn1);
        const float al2 = exp2f(m2 - mn2);
        m1 = mn1; m2 = mn2;

        float ls1 = 0.0f, ls2 = 0.0f;
        #pragma unroll
        for (int j = 0; j < 8; j++) {
            sacc[j][0] = exp2f(sacc[j][0] - mn1);
            sacc[j][1] = exp2f(sacc[j][1] - mn1);
            sacc[j][2] = exp2f(sacc[j][2] - mn2);
            sacc[j][3] = exp2f(sacc[j][3] - mn2);
            ls1 += sacc[j][0] + sacc[j][1];
            ls2 += sacc[j][2] + sacc[j][3];
        }
        ls1 += __shfl_xor_sync(0xffffffffu, ls1, 1);
        ls1 += __shfl_xor_sync(0xffffffffu, ls1, 2);
        ls2 += __shfl_xor_sync(0xffffffffu, ls2, 1);
        ls2 += __shfl_xor_sync(0xffffffffu, ls2, 2);
        l1 = l1 * al1 + ls1;
        l2 = l2 * al2 + ls2;

        #pragma unroll
        for (int j = 0; j < 8; j++) {
            O[j][0] *= al1; O[j][1] *= al1;
            O[j][2] *= al2; O[j][3] *= al2;
        }

        // ---- O += P @ V (3 terms), P from sacc regs (A-fragment layout) ----
        #pragma unroll
        for (int kk = 0; kk < 4; kk++) {
            // pack P hi/lo A-fragments for token chunk kk (S tiles 2kk, 2kk+1)
            uint32_t pah[4], pal[4];
            #pragma unroll
            for (int half = 0; half < 2; half++) {
                const float* sj = sacc[2 * kk + half];
                uint32_t h0 = pack_bf16x2(sj[0], sj[1]);
                uint32_t h1 = pack_bf16x2(sj[2], sj[3]);
                __nv_bfloat162 hb0 = *(__nv_bfloat162*)&h0;
                __nv_bfloat162 hb1 = *(__nv_bfloat162*)&h1;
                float2 f0 = __bfloat1622float2(hb0);
                float2 f1 = __bfloat1622float2(hb1);
                pah[0 + half * 2] = h0;
                pah[1 + half * 2] = h1;
                pal[0 + half * 2] = pack_bf16x2(sj[0] - f0.x, sj[1] - f0.y);
                pal[1 + half * 2] = pack_bf16x2(sj[2] - f1.x, sj[3] - f1.y);
            }
            #pragma unroll
            for (int nj = 0; nj < 4; nj++) {
                uint32_t vh[4], vl[4];
                uint32_t off = ((kk * 16 + v_rowl) * APITCH + nj * 16 + v_coff) * 2;
                ldsm_x4_trans(vh, sVh + off);
                ldsm_x4_trans(vl, sVl + off);
                mma_bf16(O[2 * nj + 0], pah, vh[0], vh[1]);
                mma_bf16(O[2 * nj + 0], pah, vl[0], vl[1]);
                mma_bf16(O[2 * nj + 0], pal, vh[0], vh[1]);
                mma_bf16(O[2 * nj + 1], pah, vh[2], vh[3]);
                mma_bf16(O[2 * nj + 1], pah, vl[2], vl[3]);
                mma_bf16(O[2 * nj + 1], pal, vh[2], vh[3]);
            }
        }
        __syncthreads();   // done reading stage st before it is overwritten
    }

    // ---- finalize + store ----
    const float i1 = 1.0f / l1;
    const float i2 = 1.0f / l2;
    #pragma unroll
    for (int j = 0; j < 8; j++) {
        const int col = cb + 8 * j + 2 * t;
        *(float2*)(Out + (size_t)(r0 + g) * H + col) =
            make_float2(O[j][0] * i1, O[j][1] * i1);
        *(float2*)(Out + (size_t)(r0 + g + 8) * H + col) =
            make_float2(O[j][2] * i2, O[j][3] * i2);
    }
}

// ---------------------------------------------------------------------------
// Launch
// Inputs (metadata order): hidden_states, wq, bq, wk, bk, wv, bv, wo, bo, mask
// ---------------------------------------------------------------------------
extern "C" void kernel_launch(void* const* d_in, const int* in_sizes, int n_in,
                              void* d_out, int out_size)
{
    const float* x    = (const float*)d_in[0];
    const float* wq   = (const float*)d_in[1];
    const float* bq   = (const float*)d_in[2];
    const float* wk   = (const float*)d_in[3];
    const float* bk   = (const float*)d_in[4];
    const float* wv   = (const float*)d_in[5];
    const float* bv   = (const float*)d_in[6];
    const float* wo   = (const float*)d_in[7];
    const float* bo   = (const float*)d_in[8];
    const void*  mask = (const void*)d_in[9];
    float* out = (float*)d_out;

    float *dq, *dk, *dv, *dattn;
    cudaGetSymbolAddress((void**)&dq, g_q);
    cudaGetSymbolAddress((void**)&dk, g_k);
    cudaGetSymbolAddress((void**)&dv, g_v);
    cudaGetSymbolAddress((void**)&dattn, g_attn);
    __nv_bfloat16 *xh, *xl, *ah, *al;
    __nv_bfloat16 *wqh, *wql, *wkh, *wkl, *wvh, *wvl, *woh, *wol;
    __nv_bfloat16 *qsh, *qsl, *ksh, *ksl, *vsh, *vsl;
    cudaGetSymbolAddress((void**)&xh, g_xh);
    cudaGetSymbolAddress((void**)&xl, g_xl);
    cudaGetSymbolAddress((void**)&ah, g_ah);
    cudaGetSymbolAddress((void**)&al, g_al);
    cudaGetSymbolAddress((void**)&wqh, g_wqh);
    cudaGetSymbolAddress((void**)&wql, g_wql);
    cudaGetSymbolAddress((void**)&wkh, g_wkh);
    cudaGetSymbolAddress((void**)&wkl, g_wkl);
    cudaGetSymbolAddress((void**)&wvh, g_wvh);
    cudaGetSymbolAddress((void**)&wvl, g_wvl);
    cudaGetSymbolAddress((void**)&woh, g_woh);
    cudaGetSymbolAddress((void**)&wol, g_wol);
    cudaGetSymbolAddress((void**)&qsh, g_qsh);
    cudaGetSymbolAddress((void**)&qsl, g_qsl);
    cudaGetSymbolAddress((void**)&ksh, g_ksh);
    cudaGetSymbolAddress((void**)&ksl, g_ksl);
    cudaGetSymbolAddress((void**)&vsh, g_vsh);
    cudaGetSymbolAddress((void**)&vsl, g_vsl);

    cudaFuncSetAttribute(gemm_mma_kernel,
                         cudaFuncAttributeMaxDynamicSharedMemorySize, GEMM_SMEM);
    cudaFuncSetAttribute(sparse_attn_mma_kernel,
                         cudaFuncAttributeMaxDynamicSharedMemorySize, AT_SMEM);

    build_blockmask_kernel<<<1, 64>>>(mask);

    const int nx4 = S * H / 4;
    const int nw4 = H * H / 4;
    split_bf16_kernel<<<nx4 / 256, 256>>>(x,  xh,  xl,  nx4);
    split_bf16_kernel<<<nw4 / 256, 256>>>(wq, wqh, wql, nw4);
    split_bf16_kernel<<<nw4 / 256, 256>>>(wk, wkh, wkl, nw4);
    split_bf16_kernel<<<nw4 / 256, 256>>>(wv, wvh, wvl, nw4);
    split_bf16_kernel<<<nw4 / 256, 256>>>(wo, woh, wol, nw4);

    dim3 gemmGrid(H / 128, S / 128);
    gemm_mma_kernel<<<gemmGrid, 256, GEMM_SMEM>>>(xh, xl, wqh, wql, bq, dq);
    gemm_mma_kernel<<<gemmGrid, 256, GEMM_SMEM>>>(xh, xl, wkh, wkl, bk, dk);
    gemm_mma_kernel<<<gemmGrid, 256, GEMM_SMEM>>>(xh, xl, wvh, wvl, bv, dv);

    // split Q/K/V for the mma attention
    split_bf16_kernel<<<nx4 / 256, 256>>>(dq, qsh, qsl, nx4);
    split_bf16_kernel<<<nx4 / 256, 256>>>(dk, ksh, ksl, nx4);
    split_bf16_kernel<<<nx4 / 256, 256>>>(dv, vsh, vsl, nx4);

    dim3 attnGrid(NB, NH);
    sparse_attn_mma_kernel<<<attnGrid, 128, AT_SMEM>>>(
        qsh, qsl, ksh, ksl, vsh, vsl, dattn);

    split_bf16_kernel<<<nx4 / 256, 256>>>(dattn, ah, al, nx4);
    gemm_mma_kernel<<<gemmGrid, 256, GEMM_SMEM>>>(ah, al, woh, wol, bo, out);
}

// round 13
// speedup vs baseline: 4.0303x; 1.1398x over previous
#include <cuda_runtime.h>
#include <cuda_bf16.h>
#include <cstdint>
#include <math.h>

// Problem constants
#define S    4096
#define H    1024
#define NH   16
#define HD   64
#define BS   64
#define NB   (S / BS)
#define KDIM 1024

// ---------------------------------------------------------------------------
// Scratch (device globals; no allocation allowed)
// ---------------------------------------------------------------------------
__device__ unsigned char g_cols[NB][NB];
__device__ int g_cnt[NB];

__device__ __align__(16) __nv_bfloat16 g_xh[S * H];
__device__ __align__(16) __nv_bfloat16 g_xl[S * H];
__device__ __align__(16) __nv_bfloat16 g_ah[S * H];
__device__ __align__(16) __nv_bfloat16 g_al[S * H];
__device__ __align__(16) __nv_bfloat16 g_wqh[H * H];
__device__ __align__(16) __nv_bfloat16 g_wql[H * H];
__device__ __align__(16) __nv_bfloat16 g_wkh[H * H];
__device__ __align__(16) __nv_bfloat16 g_wkl[H * H];
__device__ __align__(16) __nv_bfloat16 g_wvh[H * H];
__device__ __align__(16) __nv_bfloat16 g_wvl[H * H];
__device__ __align__(16) __nv_bfloat16 g_woh[H * H];
__device__ __align__(16) __nv_bfloat16 g_wol[H * H];
__device__ __align__(16) __nv_bfloat16 g_qsh[S * H];
__device__ __align__(16) __nv_bfloat16 g_qsl[S * H];
__device__ __align__(16) __nv_bfloat16 g_ksh[S * H];
__device__ __align__(16) __nv_bfloat16 g_ksl[S * H];
__device__ __align__(16) __nv_bfloat16 g_vsh[S * H];
__device__ __align__(16) __nv_bfloat16 g_vsl[S * H];

// ---------------------------------------------------------------------------
// Baseline-PTX primitives (sm_80+ ISA, compiles at compute_103)
// ---------------------------------------------------------------------------
__device__ __forceinline__ uint32_t smem_u32(const void* p) {
    uint32_t a;
    asm("{ .reg .u64 t; cvta.to.shared.u64 t, %1; cvt.u32.u64 %0, t; }"
        : "=r"(a) : "l"(p));
    return a;
}
__device__ __forceinline__ void ldsm_x4(uint32_t* r, uint32_t addr) {
    asm volatile("ldmatrix.sync.aligned.m8n8.x4.shared.b16 {%0,%1,%2,%3}, [%4];"
                 : "=r"(r[0]), "=r"(r[1]), "=r"(r[2]), "=r"(r[3]) : "r"(addr));
}
__device__ __forceinline__ void ldsm_x4_trans(uint32_t* r, uint32_t addr) {
    asm volatile("ldmatrix.sync.aligned.m8n8.x4.trans.shared.b16 {%0,%1,%2,%3}, [%4];"
                 : "=r"(r[0]), "=r"(r[1]), "=r"(r[2]), "=r"(r[3]) : "r"(addr));
}
__device__ __forceinline__ void mma_bf16(float* d, const uint32_t* a,
                                         uint32_t b0, uint32_t b1) {
    asm volatile(
        "mma.sync.aligned.m16n8k16.row.col.f32.bf16.bf16.f32 "
        "{%0,%1,%2,%3}, {%4,%5,%6,%7}, {%8,%9}, {%0,%1,%2,%3};"
        : "+f"(d[0]), "+f"(d[1]), "+f"(d[2]), "+f"(d[3])
        : "r"(a[0]), "r"(a[1]), "r"(a[2]), "r"(a[3]), "r"(b0), "r"(b1));
}
__device__ __forceinline__ void cp_async16(uint32_t dst, const void* src) {
    asm volatile("cp.async.cg.shared.global [%0], [%1], 16;"
                 :: "r"(dst), "l"(src) : "memory");
}
#define CP_COMMIT() asm volatile("cp.async.commit_group;" ::: "memory")
#define CP_WAIT(n)  asm volatile("cp.async.wait_group %0;" :: "n"(n) : "memory")

__device__ __forceinline__ uint32_t pack_bf16x2(float x, float y) {
    __nv_bfloat162 h = __floats2bfloat162_rn(x, y);
    return *(uint32_t*)&h;
}
// split v0,v1 -> hi bf16x2 word + lo bf16x2 word
__device__ __forceinline__ void split2(float v0, float v1,
                                       uint32_t& hw, uint32_t& lw) {
    __nv_bfloat16 h0 = __float2bfloat16(v0);
    __nv_bfloat16 h1 = __float2bfloat16(v1);
    __nv_bfloat162 hh(h0, h1);
    hw = *(uint32_t*)&hh;
    __nv_bfloat162 ll(__float2bfloat16(v0 - __bfloat162float(h0)),
                      __float2bfloat16(v1 - __bfloat162float(h1)));
    lw = *(uint32_t*)&ll;
}

// ---------------------------------------------------------------------------
// Block mask -> per-qblock active column lists
// ---------------------------------------------------------------------------
__global__ void build_blockmask_kernel(const void* __restrict__ mask) {
    int i = threadIdx.x;
    if (i >= NB) return;
    unsigned int w0 = *(const unsigned int*)mask;
    int mode;
    if (w0 == 0x3F800000u)      mode = 0;
    else if (w0 == 0x01010101u) mode = 1;
    else if (w0 == 0x3F803F80u) mode = 2;
    else                        mode = 3;

    int cnt = 0;
    for (int j = 0; j < NB; j++) {
        size_t idx = (size_t)(i * BS) * S + (size_t)(j * BS);
        bool on;
        if (mode == 0)      on = ((const float*)mask)[idx] != 0.0f;
        else if (mode == 1) on = ((const unsigned char*)mask)[idx] != 0;
        else if (mode == 2) on = __bfloat162float(((const __nv_bfloat16*)mask)[idx]) != 0.0f;
        else                on = ((const int*)mask)[idx] != 0;
        if (on) g_cols[i][cnt++] = (unsigned char)j;
    }
    g_cnt[i] = cnt;
}

// ---------------------------------------------------------------------------
// fp32 -> bf16 hi/lo split (inputs: x and the 4 weight matrices)
// ---------------------------------------------------------------------------
__global__ __launch_bounds__(256) void split_bf16_kernel(
    const float* __restrict__ src,
    __nv_bfloat16* __restrict__ hi, __nv_bfloat16* __restrict__ lo, int n4)
{
    int i = blockIdx.x * 256 + threadIdx.x;
    if (i >= n4) return;
    float4 v = ((const float4*)src)[i];
    uint32_t h0, l0, h1, l1;
    split2(v.x, v.y, h0, l0);
    split2(v.z, v.w, h1, l1);
    uint32_t* hp = (uint32_t*)hi;
    uint32_t* lp = (uint32_t*)lo;
    hp[2 * i + 0] = h0;
    hp[2 * i + 1] = h1;
    lp[2 * i + 0] = l0;
    lp[2 * i + 1] = l1;
}

// ---------------------------------------------------------------------------
// mma.sync bf16-split GEMM: C = A @ B^T + bias (3 terms, fp32-accurate).
// CTA tile 128x256, 512 threads = 16 warps (4 M x 4 N), warp tile 32x64.
// 3-stage cp.async pipeline, k-tile 32, pitch 40 (conflict-free ldmatrix).
// Output: either fp32 C, or bf16 hi/lo split pair (Ch/Cl) for chaining.
// Grid: (N/256, M/128) = (4, 32) -> 128 CTAs = ONE wave on 148 SMs.
// ---------------------------------------------------------------------------
#define KT      32
#define PITCH   40
#define NKT     (KDIM / KT)                 // 32
#define TA      (128 * PITCH * 2)           // 10240 B  (A tile, one of h/l)
#define TB      (256 * PITCH * 2)           // 20480 B  (B tile, one of h/l)
#define STAGEB  (2 * TA + 2 * TB)           // 61440 B
#define GEMM_SMEM (3 * STAGEB)              // 184320 B

__global__ __launch_bounds__(512) void gemm_mma_kernel(
    const __nv_bfloat16* __restrict__ Ah, const __nv_bfloat16* __restrict__ Al,
    const __nv_bfloat16* __restrict__ Bh, const __nv_bfloat16* __restrict__ Bl,
    const float* __restrict__ bias,
    float* __restrict__ C,                       // fp32 out (or null)
    __nv_bfloat16* __restrict__ Ch,              // split out hi (or null)
    __nv_bfloat16* __restrict__ Cl)              // split out lo
{
    extern __shared__ __align__(16) char gsm[];
    const uint32_t smem0 = smem_u32(gsm);

    const int tid  = threadIdx.x;
    const int lane = tid & 31;
    const int wid  = tid >> 5;
    const int wm   = wid & 3;        // 0..3  (M, 32 rows each)
    const int wn   = wid >> 2;       // 0..3  (N, 64 cols each)
    const int bx   = blockIdx.x;     // N tile (256)
    const int by   = blockIdx.y;     // M tile (128)

    float acc[2][8][4];
    #pragma unroll
    for (int i = 0; i < 2; i++)
        #pragma unroll
        for (int j = 0; j < 8; j++)
            #pragma unroll
            for (int c = 0; c < 4; c++) acc[i][j][c] = 0.0f;

    // ldmatrix per-lane offsets
    const uint32_t a_row  = wm * 32 + (lane & 15);
    const uint32_t a_koff = ((lane >> 4) << 3);
    const uint32_t b_row  = wn * 64 + ((lane >> 3) & 1) * 8 + (lane & 7);
    const uint32_t b_koff = ((lane >> 4) << 3);

    // stage loader: 3072 x 16B chunks; thread does 6
    auto load_stage = [&](int kt, int st) {
        const uint32_t sbase = smem0 + st * STAGEB;
        #pragma unroll
        for (int it = 0; it < 6; it++) {
            int f = tid + it * 512;                 // 0..3071
            if (f < 1024) {                         // A tiles (hi, lo)
                int arr = f >> 9;                   // 0=h,1=l
                int idx = f & 511;
                int row = idx >> 2;
                int ch  = idx & 3;
                const __nv_bfloat16* gb = (arr == 0 ? Ah : Al);
                cp_async16(sbase + arr * TA + (row * PITCH + ch * 8) * 2,
                           gb + (size_t)(by * 128 + row) * KDIM + kt * KT + ch * 8);
            } else {                                // B tiles (hi, lo)
                int fb  = f - 1024;                 // 0..2047
                int arr = fb >> 10;                 // 0=h,1=l
                int idx = fb & 1023;
                int row = idx >> 2;
                int ch  = idx & 3;
                const __nv_bfloat16* gb = (arr == 0 ? Bh : Bl);
                cp_async16(sbase + 2 * TA + arr * TB + (row * PITCH + ch * 8) * 2,
                           gb + (size_t)(bx * 256 + row) * KDIM + kt * KT + ch * 8);
            }
        }
    };

    load_stage(0, 0); CP_COMMIT();
    load_stage(1, 1); CP_COMMIT();

    for (int kt = 0; kt < NKT; kt++) {
        if (kt == NKT - 1) { CP_WAIT(0); } else { CP_WAIT(1); }
        __syncthreads();   // stage kt ready; all warps done with stage (kt-1)%3

        if (kt + 2 < NKT) { load_stage(kt + 2, (kt + 2) % 3); CP_COMMIT(); }

        const uint32_t sb   = smem0 + (kt % 3) * STAGEB;
        const uint32_t sA_h = sb;
        const uint32_t sA_l = sb + TA;
        const uint32_t sB_h = sb + 2 * TA;
        const uint32_t sB_l = sb + 2 * TA + TB;

        #pragma unroll
        for (int kk = 0; kk < 2; kk++) {
            const uint32_t k0 = kk * 16;

            uint32_t ah[2][4], al[2][4];
            #pragma unroll
            for (int mt = 0; mt < 2; mt++) {
                uint32_t off = ((a_row + mt * 16) * PITCH + k0 + a_koff) * 2;
                ldsm_x4(ah[mt], sA_h + off);
                ldsm_x4(al[mt], sA_l + off);
            }
            uint32_t bh[4][4], bl[4][4];
            #pragma unroll
            for (int nt2 = 0; nt2 < 4; nt2++) {
                uint32_t off = ((b_row + nt2 * 16) * PITCH + k0 + b_koff) * 2;
                ldsm_x4(bh[nt2], sB_h + off);
                ldsm_x4(bl[nt2], sB_l + off);
            }

            #pragma unroll
            for (int mt = 0; mt < 2; mt++)
                #pragma unroll
                for (int nt = 0; nt < 8; nt++) {
                    const int g = nt >> 1, h = nt & 1;
                    mma_bf16(acc[mt][nt], ah[mt], bh[g][h], bh[g][h + 2]);
                    mma_bf16(acc[mt][nt], ah[mt], bl[g][h], bl[g][h + 2]);
                    mma_bf16(acc[mt][nt], al[mt], bh[g][h], bh[g][h + 2]);
                }
        }
    }

    // epilogue
    const int m0 = by * 128 + wm * 32 + (lane >> 2);
    const int n0 = bx * 256 + wn * 64 + (lane & 3) * 2;
    #pragma unroll
    for (int mt = 0; mt < 2; mt++) {
        const int r0 = m0 + mt * 16;
        #pragma unroll
        for (int nt = 0; nt < 8; nt++) {
            const int col = n0 + nt * 8;
            const float b0 = bias[col], b1 = bias[col + 1];
            const float v00 = acc[mt][nt][0] + b0, v01 = acc[mt][nt][1] + b1;
            const float v10 = acc[mt][nt][2] + b0, v11 = acc[mt][nt][3] + b1;
            if (C) {
                *(float2*)(C + (size_t)r0 * H + col)       = make_float2(v00, v01);
                *(float2*)(C + (size_t)(r0 + 8) * H + col) = make_float2(v10, v11);
            } else {
                uint32_t hw, lw;
                split2(v00, v01, hw, lw);
                *(uint32_t*)(Ch + (size_t)r0 * H + col) = hw;
                *(uint32_t*)(Cl + (size_t)r0 * H + col) = lw;
                split2(v10, v11, hw, lw);
                *(uint32_t*)(Ch + (size_t)(r0 + 8) * H + col) = hw;
                *(uint32_t*)(Cl + (size_t)(r0 + 8) * H + col) = lw;
            }
        }
    }
}

// ---------------------------------------------------------------------------
// Block-sparse flash attention on mma.sync (bf16 3-term split).
// Grid: (NB, NH). 128 threads = 4 warps; warp handles 16 q-rows x 64 cols.
// Writes hi/lo bf16 split output directly (consumed by the O-proj GEMM).
// ---------------------------------------------------------------------------
#define APITCH   72
#define KVTILE   (64 * APITCH * 2)       // 9216 B
#define AT_SMEM  (2 * 4 * KVTILE)        // 73728 B

__global__ __launch_bounds__(128) void sparse_attn_mma_kernel(
    const __nv_bfloat16* __restrict__ Qh, const __nv_bfloat16* __restrict__ Ql,
    const __nv_bfloat16* __restrict__ Kh, const __nv_bfloat16* __restrict__ Kl,
    const __nv_bfloat16* __restrict__ Vh, const __nv_bfloat16* __restrict__ Vl,
    __nv_bfloat16* __restrict__ Oh, __nv_bfloat16* __restrict__ Ol)
{
    extern __shared__ __align__(16) char asmem[];
    const uint32_t sb0 = smem_u32(asmem);

    const int qb   = blockIdx.x;
    const int head = blockIdx.y;
    const int tid  = threadIdx.x;
    const int lane = tid & 31;
    const int wid  = tid >> 5;
    const int g    = lane >> 2;
    const int t    = lane & 3;

    const float SCALE = 0.125f * 1.44269504088896340736f;

    const int r0 = qb * BS + wid * 16;
    const int cb = head * HD;

    uint32_t qhf[4][4], qlf[4][4];
    #pragma unroll
    for (int kk = 0; kk < 4; kk++) {
        const int c0 = cb + kk * 16 + 2 * t;
        qhf[kk][0] = *(const uint32_t*)&Qh[(size_t)(r0 + g) * H + c0];
        qhf[kk][1] = *(const uint32_t*)&Qh[(size_t)(r0 + g + 8) * H + c0];
        qhf[kk][2] = *(const uint32_t*)&Qh[(size_t)(r0 + g) * H + c0 + 8];
        qhf[kk][3] = *(const uint32_t*)&Qh[(size_t)(r0 + g + 8) * H + c0 + 8];
        qlf[kk][0] = *(const uint32_t*)&Ql[(size_t)(r0 + g) * H + c0];
        qlf[kk][1] = *(const uint32_t*)&Ql[(size_t)(r0 + g + 8) * H + c0];
        qlf[kk][2] = *(const uint32_t*)&Ql[(size_t)(r0 + g) * H + c0 + 8];
        qlf[kk][3] = *(const uint32_t*)&Ql[(size_t)(r0 + g + 8) * H + c0 + 8];
    }

    const uint32_t b_rowl = ((lane >> 3) & 1) * 8 + (lane & 7);
    const uint32_t b_koff = (lane >> 4) * 8;
    const uint32_t v_rowl = b_rowl;
    const uint32_t v_coff = b_koff;

    float O[8][4];
    #pragma unroll
    for (int j = 0; j < 8; j++)
        #pragma unroll
        for (int c = 0; c < 4; c++) O[j][c] = 0.0f;
    float m1 = -INFINITY, m2 = -INFINITY, l1 = 0.0f, l2 = 0.0f;

    const int cnt = g_cnt[qb];
    const __nv_bfloat16* kvsrc[4] = { Kh, Kl, Vh, Vl };

    auto load_stage = [&](int jblk, int st) {
        const int kr0 = jblk * BS;
        const uint32_t sbase = sb0 + st * 4 * KVTILE;
        #pragma unroll
        for (int it = 0; it < 16; it++) {
            int f    = tid + it * 128;
            int arr  = f >> 9;
            int row  = (f >> 3) & 63;
            int ch   = f & 7;
            cp_async16(sbase + arr * KVTILE + (row * APITCH + ch * 8) * 2,
                       kvsrc[arr] + (size_t)(kr0 + row) * H + cb + ch * 8);
        }
    };

    load_stage(g_cols[qb][0], 0); CP_COMMIT();

    for (int jj = 0; jj < cnt; jj++) {
        const int st = jj & 1;
        if (jj + 1 < cnt) { load_stage(g_cols[qb][jj + 1], st ^ 1); CP_COMMIT(); }
        if (jj + 1 < cnt) { CP_WAIT(1); } else { CP_WAIT(0); }
        __syncthreads();

        const uint32_t sKh = sb0 + st * 4 * KVTILE + 0 * KVTILE;
        const uint32_t sKl = sb0 + st * 4 * KVTILE + 1 * KVTILE;
        const uint32_t sVh = sb0 + st * 4 * KVTILE + 2 * KVTILE;
        const uint32_t sVl = sb0 + st * 4 * KVTILE + 3 * KVTILE;

        float sacc[8][4];
        #pragma unroll
        for (int j = 0; j < 8; j++)
            #pragma unroll
            for (int c = 0; c < 4; c++) sacc[j][c] = 0.0f;

        #pragma unroll
        for (int kk = 0; kk < 4; kk++) {
            uint32_t kh[4][4], kl[4][4];
            #pragma unroll
            for (int g4 = 0; g4 < 4; g4++) {
                uint32_t off = ((g4 * 16 + b_rowl) * APITCH + kk * 16 + b_koff) * 2;
                ldsm_x4(kh[g4], sKh + off);
                ldsm_x4(kl[g4], sKl + off);
            }
            #pragma unroll
            for (int nt = 0; nt < 8; nt++) {
                const int g4 = nt >> 1, h = nt & 1;
                mma_bf16(sacc[nt], qhf[kk], kh[g4][h], kh[g4][h + 2]);
                mma_bf16(sacc[nt], qhf[kk], kl[g4][h], kl[g4][h + 2]);
                mma_bf16(sacc[nt], qlf[kk], kh[g4][h], kh[g4][h + 2]);
            }
        }

        #pragma unroll
        for (int j = 0; j < 8; j++)
            #pragma unroll
            for (int c = 0; c < 4; c++) sacc[j][c] *= SCALE;

        float mx1 = sacc[0][0], mx2 = sacc[0][2];
        #pragma unroll
        for (int j = 0; j < 8; j++) {
            mx1 = fmaxf(mx1, fmaxf(sacc[j][0], sacc[j][1]));
            mx2 = fmaxf(mx2, fmaxf(sacc[j][2], sacc[j][3]));
        }
        mx1 = fmaxf(mx1, __shfl_xor_sync(0xffffffffu, mx1, 1));
        mx1 = fmaxf(mx1, __shfl_xor_sync(0xffffffffu, mx1, 2));
        mx2 = fmaxf(mx2, __shfl_xor_sync(0xffffffffu, mx2, 1));
        mx2 = fmaxf(mx2, __shfl_xor_sync(0xffffffffu, mx2, 2));

        const float mn1 = fmaxf(m1, mx1);
        const float mn2 = fmaxf(m2, mx2);
        const float al1 = exp2f(m1 - mn1);
        const float al2 = exp2f(m2 - mn2);
        m1 = mn1; m2 = mn2;

        float ls1 = 0.0f, ls2 = 0.0f;
        #pragma unroll
        for (int j = 0; j < 8; j++) {
            sacc[j][0] = exp2f(sacc[j][0] - mn1);
            sacc[j][1] = exp2f(sacc[j][1] - mn1);
            sacc[j][2] = exp2f(sacc[j][2] - mn2);
            sacc[j][3] = exp2f(sacc[j][3] - mn2);
            ls1 += sacc[j][0] + sacc[j][1];
            ls2 += sacc[j][2] + sacc[j][3];
        }
        ls1 += __shfl_xor_sync(0xffffffffu, ls1, 1);
        ls1 += __shfl_xor_sync(0xffffffffu, ls1, 2);
        ls2 += __shfl_xor_sync(0xffffffffu, ls2, 1);
        ls2 += __shfl_xor_sync(0xffffffffu, ls2, 2);
        l1 = l1 * al1 + ls1;
        l2 = l2 * al2 + ls2;

        #pragma unroll
        for (int j = 0; j < 8; j++) {
            O[j][0] *= al1; O[j][1] *= al1;
            O[j][2] *= al2; O[j][3] *= al2;
        }

        #pragma unroll
        for (int kk = 0; kk < 4; kk++) {
            uint32_t pah[4], pal[4];
            #pragma unroll
            for (int half = 0; half < 2; half++) {
                const float* sj = sacc[2 * kk + half];
                uint32_t h0 = pack_bf16x2(sj[0], sj[1]);
                uint32_t h1 = pack_bf16x2(sj[2], sj[3]);
                __nv_bfloat162 hb0 = *(__nv_bfloat162*)&h0;
                __nv_bfloat162 hb1 = *(__nv_bfloat162*)&h1;
                float2 f0 = __bfloat1622float2(hb0);
                float2 f1 = __bfloat1622float2(hb1);
                pah[0 + half * 2] = h0;
                pah[1 + half * 2] = h1;
                pal[0 + half * 2] = pack_bf16x2(sj[0] - f0.x, sj[1] - f0.y);
                pal[1 + half * 2] = pack_bf16x2(sj[2] - f1.x, sj[3] - f1.y);
            }
            #pragma unroll
            for (int nj = 0; nj < 4; nj++) {
                uint32_t vh[4], vl[4];
                uint32_t off = ((kk * 16 + v_rowl) * APITCH + nj * 16 + v_coff) * 2;
                ldsm_x4_trans(vh, sVh + off);
                ldsm_x4_trans(vl, sVl + off);
                mma_bf16(O[2 * nj + 0], pah, vh[0], vh[1]);
                mma_bf16(O[2 * nj + 0], pah, vl[0], vl[1]);
                mma_bf16(O[2 * nj + 0], pal, vh[0], vh[1]);
                mma_bf16(O[2 * nj + 1], pah, vh[2], vh[3]);
                mma_bf16(O[2 * nj + 1], pah, vl[2], vl[3]);
                mma_bf16(O[2 * nj + 1], pal, vh[2], vh[3]);
            }
        }
        __syncthreads();
    }

    // finalize + store hi/lo split directly
    const float i1 = 1.0f / l1;
    const float i2 = 1.0f / l2;
    #pragma unroll
    for (int j = 0; j < 8; j++) {
        const int col = cb + 8 * j + 2 * t;
        uint32_t hw, lw;
        split2(O[j][0] * i1, O[j][1] * i1, hw, lw);
        *(uint32_t*)(Oh + (size_t)(r0 + g) * H + col) = hw;
        *(uint32_t*)(Ol + (size_t)(r0 + g) * H + col) = lw;
        split2(O[j][2] * i2, O[j][3] * i2, hw, lw);
        *(uint32_t*)(Oh + (size_t)(r0 + g + 8) * H + col) = hw;
        *(uint32_t*)(Ol + (size_t)(r0 + g + 8) * H + col) = lw;
    }
}

// ---------------------------------------------------------------------------
// Launch
// Inputs (metadata order): hidden_states, wq, bq, wk, bk, wv, bv, wo, bo, mask
// ---------------------------------------------------------------------------
extern "C" void kernel_launch(void* const* d_in, const int* in_sizes, int n_in,
                              void* d_out, int out_size)
{
    const float* x    = (const float*)d_in[0];
    const float* wq   = (const float*)d_in[1];
    const float* bq   = (const float*)d_in[2];
    const float* wk   = (const float*)d_in[3];
    const float* bk   = (const float*)d_in[4];
    const float* wv   = (const float*)d_in[5];
    const float* bv   = (const float*)d_in[6];
    const float* wo   = (const float*)d_in[7];
    const float* bo   = (const float*)d_in[8];
    const void*  mask = (const void*)d_in[9];
    float* out = (float*)d_out;

    __nv_bfloat16 *xh, *xl, *ah, *al;
    __nv_bfloat16 *wqh, *wql, *wkh, *wkl, *wvh, *wvl, *woh, *wol;
    __nv_bfloat16 *qsh, *qsl, *ksh, *ksl, *vsh, *vsl;
    cudaGetSymbolAddress((void**)&xh, g_xh);
    cudaGetSymbolAddress((void**)&xl, g_xl);
    cudaGetSymbolAddress((void**)&ah, g_ah);
    cudaGetSymbolAddress((void**)&al, g_al);
    cudaGetSymbolAddress((void**)&wqh, g_wqh);
    cudaGetSymbolAddress((void**)&wql, g_wql);
    cudaGetSymbolAddress((void**)&wkh, g_wkh);
    cudaGetSymbolAddress((void**)&wkl, g_wkl);
    cudaGetSymbolAddress((void**)&wvh, g_wvh);
    cudaGetSymbolAddress((void**)&wvl, g_wvl);
    cudaGetSymbolAddress((void**)&woh, g_woh);
    cudaGetSymbolAddress((void**)&wol, g_wol);
    cudaGetSymbolAddress((void**)&qsh, g_qsh);
    cudaGetSymbolAddress((void**)&qsl, g_qsl);
    cudaGetSymbolAddress((void**)&ksh, g_ksh);
    cudaGetSymbolAddress((void**)&ksl, g_ksl);
    cudaGetSymbolAddress((void**)&vsh, g_vsh);
    cudaGetSymbolAddress((void**)&vsl, g_vsl);

    cudaFuncSetAttribute(gemm_mma_kernel,
                         cudaFuncAttributeMaxDynamicSharedMemorySize, GEMM_SMEM);
    cudaFuncSetAttribute(sparse_attn_mma_kernel,
                         cudaFuncAttributeMaxDynamicSharedMemorySize, AT_SMEM);

    build_blockmask_kernel<<<1, 64>>>(mask);

    const int nx4 = S * H / 4;
    const int nw4 = H * H / 4;
    split_bf16_kernel<<<nx4 / 256, 256>>>(x,  xh,  xl,  nx4);
    split_bf16_kernel<<<nw4 / 256, 256>>>(wq, wqh, wql, nw4);
    split_bf16_kernel<<<nw4 / 256, 256>>>(wk, wkh, wkl, nw4);
    split_bf16_kernel<<<nw4 / 256, 256>>>(wv, wvh, wvl, nw4);
    split_bf16_kernel<<<nw4 / 256, 256>>>(wo, woh, wol, nw4);

    dim3 gemmGrid(H / 256, S / 128);   // (4, 32) = 128 CTAs
    // QKV projections write bf16 hi/lo splits directly
    gemm_mma_kernel<<<gemmGrid, 512, GEMM_SMEM>>>(xh, xl, wqh, wql, bq,
                                                  nullptr, qsh, qsl);
    gemm_mma_kernel<<<gemmGrid, 512, GEMM_SMEM>>>(xh, xl, wkh, wkl, bk,
                                                  nullptr, ksh, ksl);
    gemm_mma_kernel<<<gemmGrid, 512, GEMM_SMEM>>>(xh, xl, wvh, wvl, bv,
                                                  nullptr, vsh, vsl);

    dim3 attnGrid(NB, NH);
    sparse_attn_mma_kernel<<<attnGrid, 128, AT_SMEM>>>(
        qsh, qsl, ksh, ksl, vsh, vsl, ah, al);

    // O projection writes fp32 output
    gemm_mma_kernel<<<gemmGrid, 512, GEMM_SMEM>>>(ah, al, woh, wol, bo,
                                                  out, nullptr, nullptr);
}

// round 14
// speedup vs baseline: 5.7643x; 1.4303x over previous
#include <cuda_runtime.h>
#include <cuda_fp16.h>
#include <cstdint>
#include <math.h>

// Problem constants
#define S    4096
#define H    1024
#define NH   16
#define HD   64
#define BS   64
#define NB   (S / BS)
#define KDIM 1024

// ---------------------------------------------------------------------------
// Scratch (device globals; no allocation allowed)
// ---------------------------------------------------------------------------
__device__ unsigned char g_cols[NB][NB];
__device__ int g_cnt[NB];

__device__ __align__(16) __half g_xh[S * H];
__device__ __align__(16) __half g_xl[S * H];
__device__ __align__(16) __half g_wqh[H * H];
__device__ __align__(16) __half g_wkh[H * H];
__device__ __align__(16) __half g_wvh[H * H];
__device__ __align__(16) __half g_woh[H * H];
__device__ __align__(16) __half g_qsh[S * H];
__device__ __align__(16) __half g_qsl[S * H];
__device__ __align__(16) __half g_ksh[S * H];
__device__ __align__(16) __half g_vsh[S * H];
__device__ __align__(16) __half g_ah[S * H];
__device__ __align__(16) __half g_al[S * H];

// ---------------------------------------------------------------------------
// Baseline-PTX primitives (sm_80+ ISA, compiles at compute_103)
// ---------------------------------------------------------------------------
__device__ __forceinline__ uint32_t smem_u32(const void* p) {
    uint32_t a;
    asm("{ .reg .u64 t; cvta.to.shared.u64 t, %1; cvt.u32.u64 %0, t; }"
        : "=r"(a) : "l"(p));
    return a;
}
__device__ __forceinline__ void ldsm_x4(uint32_t* r, uint32_t addr) {
    asm volatile("ldmatrix.sync.aligned.m8n8.x4.shared.b16 {%0,%1,%2,%3}, [%4];"
                 : "=r"(r[0]), "=r"(r[1]), "=r"(r[2]), "=r"(r[3]) : "r"(addr));
}
__device__ __forceinline__ void ldsm_x4_trans(uint32_t* r, uint32_t addr) {
    asm volatile("ldmatrix.sync.aligned.m8n8.x4.trans.shared.b16 {%0,%1,%2,%3}, [%4];"
                 : "=r"(r[0]), "=r"(r[1]), "=r"(r[2]), "=r"(r[3]) : "r"(addr));
}
__device__ __forceinline__ void mma_f16(float* d, const uint32_t* a,
                                        uint32_t b0, uint32_t b1) {
    asm volatile(
        "mma.sync.aligned.m16n8k16.row.col.f32.f16.f16.f32 "
        "{%0,%1,%2,%3}, {%4,%5,%6,%7}, {%8,%9}, {%0,%1,%2,%3};"
        : "+f"(d[0]), "+f"(d[1]), "+f"(d[2]), "+f"(d[3])
        : "r"(a[0]), "r"(a[1]), "r"(a[2]), "r"(a[3]), "r"(b0), "r"(b1));
}
__device__ __forceinline__ void cp_async16(uint32_t dst, const void* src) {
    asm volatile("cp.async.cg.shared.global [%0], [%1], 16;"
                 :: "r"(dst), "l"(src) : "memory");
}
#define CP_COMMIT() asm volatile("cp.async.commit_group;" ::: "memory")
#define CP_WAIT(n)  asm volatile("cp.async.wait_group %0;" :: "n"(n) : "memory")

// split v0,v1 -> fp16 hi pair word + fp16 lo pair word
__device__ __forceinline__ void split2h(float v0, float v1,
                                        uint32_t& hw, uint32_t& lw) {
    __half h0 = __float2half(v0);
    __half h1 = __float2half(v1);
    __half2 hh(h0, h1);
    hw = *(uint32_t*)&hh;
    __half2 ll(__float2half(v0 - __half2float(h0)),
               __float2half(v1 - __half2float(h1)));
    lw = *(uint32_t*)&ll;
}
__device__ __forceinline__ uint32_t pack_h2(float x, float y) {
    __half2 h = __floats2half2_rn(x, y);
    return *(uint32_t*)&h;
}

// ---------------------------------------------------------------------------
// Block mask -> per-qblock active column lists
// ---------------------------------------------------------------------------
__global__ void build_blockmask_kernel(const void* __restrict__ mask) {
    int i = threadIdx.x;
    if (i >= NB) return;
    unsigned int w0 = *(const unsigned int*)mask;
    int mode;
    if (w0 == 0x3F800000u)      mode = 0;
    else if (w0 == 0x01010101u) mode = 1;
    else if (w0 == 0x3F803F80u) mode = 2;
    else                        mode = 3;

    int cnt = 0;
    for (int j = 0; j < NB; j++) {
        size_t idx = (size_t)(i * BS) * S + (size_t)(j * BS);
        bool on;
        if (mode == 0)      on = ((const float*)mask)[idx] != 0.0f;
        else if (mode == 1) on = ((const unsigned char*)mask)[idx] != 0;
        else if (mode == 2) on = (((const unsigned short*)mask)[idx] & 0x7FFFu) != 0;
        else                on = ((const int*)mask)[idx] != 0;
        if (on) g_cols[i][cnt++] = (unsigned char)j;
    }
    g_cnt[i] = cnt;
}

// ---------------------------------------------------------------------------
// fp32 -> fp16 hi/lo split (for x)
// ---------------------------------------------------------------------------
__global__ __launch_bounds__(256) void split_f16_kernel(
    const float* __restrict__ src,
    __half* __restrict__ hi, __half* __restrict__ lo, int n4)
{
    int i = blockIdx.x * 256 + threadIdx.x;
    if (i >= n4) return;
    float4 v = ((const float4*)src)[i];
    uint32_t h0, l0, h1, l1;
    split2h(v.x, v.y, h0, l0);
    split2h(v.z, v.w, h1, l1);
    ((uint32_t*)hi)[2 * i + 0] = h0;
    ((uint32_t*)hi)[2 * i + 1] = h1;
    ((uint32_t*)lo)[2 * i + 0] = l0;
    ((uint32_t*)lo)[2 * i + 1] = l1;
}
// fp32 -> fp16 convert (for weights, hi only)
__global__ __launch_bounds__(256) void conv_f16_kernel(
    const float* __restrict__ src, __half* __restrict__ dst, int n4)
{
    int i = blockIdx.x * 256 + threadIdx.x;
    if (i >= n4) return;
    float4 v = ((const float4*)src)[i];
    ((uint32_t*)dst)[2 * i + 0] = pack_h2(v.x, v.y);
    ((uint32_t*)dst)[2 * i + 1] = pack_h2(v.z, v.w);
}

// ---------------------------------------------------------------------------
// fp16 2-term GEMM core: C = A @ B^T + bias, terms Ah@Bh + Al@Bh.
// CTA tile 128x256, 512 threads = 16 warps (4 M x 4 N), warp tile 32x64.
// 3-stage cp.async pipeline, k-tile 32, pitch 40.
// ---------------------------------------------------------------------------
#define KT      32
#define PITCH   40
#define NKT     (KDIM / KT)                 // 32
#define TA      (128 * PITCH * 2)           // 10240 B
#define TB      (256 * PITCH * 2)           // 20480 B
#define STAGEB  (2 * TA + TB)               // 40960 B
#define GEMM_SMEM (3 * STAGEB)              // 122880 B

// mode: QKV fused (grid.x = 12) writes fp16 outputs; O-proj (grid.x = 4)
// writes fp32 out. Selected by the 'out32' pointer.
__global__ __launch_bounds__(512) void gemm_f16_kernel(
    const __half* __restrict__ Ah, const __half* __restrict__ Al,
    const float* __restrict__ b0, const float* __restrict__ b1,
    const float* __restrict__ b2,
    float* __restrict__ out32)
{
    extern __shared__ __align__(16) char gsm[];
    const uint32_t smem0 = smem_u32(gsm);

    const int tid  = threadIdx.x;
    const int lane = tid & 31;
    const int wid  = tid >> 5;
    const int wm   = wid & 3;
    const int wn   = wid >> 2;
    const int by   = blockIdx.y;

    int mat, bxn;
    const __half* Bh;
    const float* bias;
    if (out32) {
        mat = 3; bxn = blockIdx.x;
        Bh = g_woh; bias = b0;
    } else {
        mat = blockIdx.x >> 2; bxn = blockIdx.x & 3;
        Bh = (mat == 0) ? g_wqh : (mat == 1) ? g_wkh : g_wvh;
        bias = (mat == 0) ? b0 : (mat == 1) ? b1 : b2;
    }

    float acc[2][8][4];
    #pragma unroll
    for (int i = 0; i < 2; i++)
        #pragma unroll
        for (int j = 0; j < 8; j++)
            #pragma unroll
            for (int c = 0; c < 4; c++) acc[i][j][c] = 0.0f;

    const uint32_t a_row  = wm * 32 + (lane & 15);
    const uint32_t a_koff = ((lane >> 4) << 3);
    const uint32_t b_row  = wn * 64 + ((lane >> 3) & 1) * 8 + (lane & 7);
    const uint32_t b_koff = ((lane >> 4) << 3);

    // stage loader: 2048 x 16B chunks; thread does 4
    auto load_stage = [&](int kt, int st) {
        const uint32_t sbase = smem0 + st * STAGEB;
        #pragma unroll
        for (int it = 0; it < 4; it++) {
            int f = tid + it * 512;                 // 0..2047
            if (f < 1024) {                         // A tiles (hi, lo)
                int arr = f >> 9;
                int idx = f & 511;
                int row = idx >> 2;
                int ch  = idx & 3;
                const __half* gb = (arr == 0 ? Ah : Al);
                cp_async16(sbase + arr * TA + (row * PITCH + ch * 8) * 2,
                           gb + (size_t)(by * 128 + row) * KDIM + kt * KT + ch * 8);
            } else {                                // B tile (hi)
                int idx = f - 1024;                 // 0..1023
                int row = idx >> 2;
                int ch  = idx & 3;
                cp_async16(sbase + 2 * TA + (row * PITCH + ch * 8) * 2,
                           Bh + (size_t)(bxn * 256 + row) * KDIM + kt * KT + ch * 8);
            }
        }
    };

    load_stage(0, 0); CP_COMMIT();
    load_stage(1, 1); CP_COMMIT();

    for (int kt = 0; kt < NKT; kt++) {
        if (kt == NKT - 1) { CP_WAIT(0); } else { CP_WAIT(1); }
        __syncthreads();

        if (kt + 2 < NKT) { load_stage(kt + 2, (kt + 2) % 3); CP_COMMIT(); }

        const uint32_t sb   = smem0 + (kt % 3) * STAGEB;
        const uint32_t sA_h = sb;
        const uint32_t sA_l = sb + TA;
        const uint32_t sB_h = sb + 2 * TA;

        #pragma unroll
        for (int kk = 0; kk < 2; kk++) {
            const uint32_t k0 = kk * 16;

            uint32_t ah[2][4], al[2][4];
            #pragma unroll
            for (int mt = 0; mt < 2; mt++) {
                uint32_t off = ((a_row + mt * 16) * PITCH + k0 + a_koff) * 2;
                ldsm_x4(ah[mt], sA_h + off);
                ldsm_x4(al[mt], sA_l + off);
            }
            uint32_t bh[4][4];
            #pragma unroll
            for (int nt2 = 0; nt2 < 4; nt2++) {
                uint32_t off = ((b_row + nt2 * 16) * PITCH + k0 + b_koff) * 2;
                ldsm_x4(bh[nt2], sB_h + off);
            }

            #pragma unroll
            for (int mt = 0; mt < 2; mt++)
                #pragma unroll
                for (int nt = 0; nt < 8; nt++) {
                    const int g = nt >> 1, h = nt & 1;
                    mma_f16(acc[mt][nt], ah[mt], bh[g][h], bh[g][h + 2]);
                    mma_f16(acc[mt][nt], al[mt], bh[g][h], bh[g][h + 2]);
                }
        }
    }

    // epilogue
    const int m0 = by * 128 + wm * 32 + (lane >> 2);
    const int n0 = bxn * 256 + wn * 64 + (lane & 3) * 2;
    #pragma unroll
    for (int mt = 0; mt < 2; mt++) {
        const int r0 = m0 + mt * 16;
        #pragma unroll
        for (int nt = 0; nt < 8; nt++) {
            const int col = n0 + nt * 8;
            const float bb0 = bias[col], bb1 = bias[col + 1];
            const float v00 = acc[mt][nt][0] + bb0, v01 = acc[mt][nt][1] + bb1;
            const float v10 = acc[mt][nt][2] + bb0, v11 = acc[mt][nt][3] + bb1;
            if (mat == 3) {                // O projection -> fp32
                *(float2*)(out32 + (size_t)r0 * H + col)       = make_float2(v00, v01);
                *(float2*)(out32 + (size_t)(r0 + 8) * H + col) = make_float2(v10, v11);
            } else if (mat == 0) {         // Q -> hi/lo pair
                uint32_t hw, lw;
                split2h(v00, v01, hw, lw);
                *(uint32_t*)(g_qsh + (size_t)r0 * H + col) = hw;
                *(uint32_t*)(g_qsl + (size_t)r0 * H + col) = lw;
                split2h(v10, v11, hw, lw);
                *(uint32_t*)(g_qsh + (size_t)(r0 + 8) * H + col) = hw;
                *(uint32_t*)(g_qsl + (size_t)(r0 + 8) * H + col) = lw;
            } else {                        // K or V -> hi only
                __half* dst = (mat == 1) ? g_ksh : g_vsh;
                *(uint32_t*)(dst + (size_t)r0 * H + col)       = pack_h2(v00, v01);
                *(uint32_t*)(dst + (size_t)(r0 + 8) * H + col) = pack_h2(v10, v11);
            }
        }
    }
}

// ---------------------------------------------------------------------------
// Block-sparse flash attention on mma.sync (fp16, 2-term QK, 2-term PV).
// Grid: (NB, NH). 128 threads = 4 warps; warp handles 16 q-rows x 64 cols.
// K/V tiles hi-only: stage = 2 tiles, 2-stage cp.async.
// ---------------------------------------------------------------------------
#define APITCH   72
#define KVTILE   (64 * APITCH * 2)       // 9216 B
#define AT_SMEM  (2 * 2 * KVTILE)        // 36864 B

__global__ __launch_bounds__(128) void sparse_attn_mma_kernel()
{
    extern __shared__ __align__(16) char asmem[];
    const uint32_t sb0 = smem_u32(asmem);

    const int qb   = blockIdx.x;
    const int head = blockIdx.y;
    const int tid  = threadIdx.x;
    const int lane = tid & 31;
    const int wid  = tid >> 5;
    const int g    = lane >> 2;
    const int t    = lane & 3;

    const float SCALE = 0.125f * 1.44269504088896340736f;

    const int r0 = qb * BS + wid * 16;
    const int cb = head * HD;

    uint32_t qhf[4][4], qlf[4][4];
    #pragma unroll
    for (int kk = 0; kk < 4; kk++) {
        const int c0 = cb + kk * 16 + 2 * t;
        qhf[kk][0] = *(const uint32_t*)&g_qsh[(size_t)(r0 + g) * H + c0];
        qhf[kk][1] = *(const uint32_t*)&g_qsh[(size_t)(r0 + g + 8) * H + c0];
        qhf[kk][2] = *(const uint32_t*)&g_qsh[(size_t)(r0 + g) * H + c0 + 8];
        qhf[kk][3] = *(const uint32_t*)&g_qsh[(size_t)(r0 + g + 8) * H + c0 + 8];
        qlf[kk][0] = *(const uint32_t*)&g_qsl[(size_t)(r0 + g) * H + c0];
        qlf[kk][1] = *(const uint32_t*)&g_qsl[(size_t)(r0 + g + 8) * H + c0];
        qlf[kk][2] = *(const uint32_t*)&g_qsl[(size_t)(r0 + g) * H + c0 + 8];
        qlf[kk][3] = *(const uint32_t*)&g_qsl[(size_t)(r0 + g + 8) * H + c0 + 8];
    }

    const uint32_t b_rowl = ((lane >> 3) & 1) * 8 + (lane & 7);
    const uint32_t b_koff = (lane >> 4) * 8;

    float O[8][4];
    #pragma unroll
    for (int j = 0; j < 8; j++)
        #pragma unroll
        for (int c = 0; c < 4; c++) O[j][c] = 0.0f;
    float m1 = -INFINITY, m2 = -INFINITY, l1 = 0.0f, l2 = 0.0f;

    const int cnt = g_cnt[qb];

    auto load_stage = [&](int jblk, int st) {
        const int kr0 = jblk * BS;
        const uint32_t sbase = sb0 + st * 2 * KVTILE;
        #pragma unroll
        for (int it = 0; it < 8; it++) {
            int f    = tid + it * 128;        // 0..1023
            int arr  = f >> 9;                // 0=K, 1=V
            int row  = (f >> 3) & 63;
            int ch   = f & 7;
            const __half* gb = arr == 0 ? g_ksh : g_vsh;
            cp_async16(sbase + arr * KVTILE + (row * APITCH + ch * 8) * 2,
                       gb + (size_t)(kr0 + row) * H + cb + ch * 8);
        }
    };

    load_stage(g_cols[qb][0], 0); CP_COMMIT();

    for (int jj = 0; jj < cnt; jj++) {
        const int st = jj & 1;
        if (jj + 1 < cnt) { load_stage(g_cols[qb][jj + 1], st ^ 1); CP_COMMIT(); }
        if (jj + 1 < cnt) { CP_WAIT(1); } else { CP_WAIT(0); }
        __syncthreads();

        const uint32_t sKh = sb0 + st * 2 * KVTILE;
        const uint32_t sVh = sKh + KVTILE;

        float sacc[8][4];
        #pragma unroll
        for (int j = 0; j < 8; j++)
            #pragma unroll
            for (int c = 0; c < 4; c++) sacc[j][c] = 0.0f;

        #pragma unroll
        for (int kk = 0; kk < 4; kk++) {
            uint32_t kh[4][4];
            #pragma unroll
            for (int g4 = 0; g4 < 4; g4++) {
                uint32_t off = ((g4 * 16 + b_rowl) * APITCH + kk * 16 + b_koff) * 2;
                ldsm_x4(kh[g4], sKh + off);
            }
            #pragma unroll
            for (int nt = 0; nt < 8; nt++) {
                const int g4 = nt >> 1, h = nt & 1;
                mma_f16(sacc[nt], qhf[kk], kh[g4][h], kh[g4][h + 2]);
                mma_f16(sacc[nt], qlf[kk], kh[g4][h], kh[g4][h + 2]);
            }
        }

        #pragma unroll
        for (int j = 0; j < 8; j++)
            #pragma unroll
            for (int c = 0; c < 4; c++) sacc[j][c] *= SCALE;

        float mx1 = sacc[0][0], mx2 = sacc[0][2];
        #pragma unroll
        for (int j = 0; j < 8; j++) {
            mx1 = fmaxf(mx1, fmaxf(sacc[j][0], sacc[j][1]));
            mx2 = fmaxf(mx2, fmaxf(sacc[j][2], sacc[j][3]));
        }
        mx1 = fmaxf(mx1, __shfl_xor_sync(0xffffffffu, mx1, 1));
        mx1 = fmaxf(mx1, __shfl_xor_sync(0xffffffffu, mx1, 2));
        mx2 = fmaxf(mx2, __shfl_xor_sync(0xffffffffu, mx2, 1));
        mx2 = fmaxf(mx2, __shfl_xor_sync(0xffffffffu, mx2, 2));

        const float mn1 = fmaxf(m1, mx1);
        const float mn2 = fmaxf(m2, mx2);
        const float al1 = exp2f(m1 - mn1);
        const float al2 = exp2f(m2 - mn2);
        m1 = mn1; m2 = mn2;

        float ls1 = 0.0f, ls2 = 0.0f;
        #pragma unroll
        for (int j = 0; j < 8; j++) {
            sacc[j][0] = exp2f(sacc[j][0] - mn1);
            sacc[j][1] = exp2f(sacc[j][1] - mn1);
            sacc[j][2] = exp2f(sacc[j][2] - mn2);
            sacc[j][3] = exp2f(sacc[j][3] - mn2);
            ls1 += sacc[j][0] + sacc[j][1];
            ls2 += sacc[j][2] + sacc[j][3];
        }
        ls1 += __shfl_xor_sync(0xffffffffu, ls1, 1);
        ls1 += __shfl_xor_sync(0xffffffffu, ls1, 2);
        ls2 += __shfl_xor_sync(0xffffffffu, ls2, 1);
        ls2 += __shfl_xor_sync(0xffffffffu, ls2, 2);
        l1 = l1 * al1 + ls1;
        l2 = l2 * al2 + ls2;

        #pragma unroll
        for (int j = 0; j < 8; j++) {
            O[j][0] *= al1; O[j][1] *= al1;
            O[j][2] *= al2; O[j][3] *= al2;
        }

        #pragma unroll
        for (int kk = 0; kk < 4; kk++) {
            uint32_t pah[4], pal[4];
            #pragma unroll
            for (int half = 0; half < 2; half++) {
                const float* sj = sacc[2 * kk + half];
                uint32_t h0, l0c, h1, l1c;
                split2h(sj[0], sj[1], h0, l0c);
                split2h(sj[2], sj[3], h1, l1c);
                pah[0 + half * 2] = h0;
                pah[1 + half * 2] = h1;
                pal[0 + half * 2] = l0c;
                pal[1 + half * 2] = l1c;
            }
            #pragma unroll
            for (int nj = 0; nj < 4; nj++) {
                uint32_t vh[4];
                uint32_t off = ((kk * 16 + b_rowl) * APITCH + nj * 16 + b_koff) * 2;
                ldsm_x4_trans(vh, sVh + off);
                mma_f16(O[2 * nj + 0], pah, vh[0], vh[1]);
                mma_f16(O[2 * nj + 0], pal, vh[0], vh[1]);
                mma_f16(O[2 * nj + 1], pah, vh[2], vh[3]);
                mma_f16(O[2 * nj + 1], pal, vh[2], vh[3]);
            }
        }
        __syncthreads();
    }

    // finalize + store hi/lo split for the O-projection
    const float i1 = 1.0f / l1;
    const float i2 = 1.0f / l2;
    #pragma unroll
    for (int j = 0; j < 8; j++) {
        const int col = cb + 8 * j + 2 * t;
        uint32_t hw, lw;
        split2h(O[j][0] * i1, O[j][1] * i1, hw, lw);
        *(uint32_t*)(g_ah + (size_t)(r0 + g) * H + col) = hw;
        *(uint32_t*)(g_al + (size_t)(r0 + g) * H + col) = lw;
        split2h(O[j][2] * i2, O[j][3] * i2, hw, lw);
        *(uint32_t*)(g_ah + (size_t)(r0 + g + 8) * H + col) = hw;
        *(uint32_t*)(g_al + (size_t)(r0 + g + 8) * H + col) = lw;
    }
}

// ---------------------------------------------------------------------------
// Launch
// Inputs (metadata order): hidden_states, wq, bq, wk, bk, wv, bv, wo, bo, mask
// ---------------------------------------------------------------------------
extern "C" void kernel_launch(void* const* d_in, const int* in_sizes, int n_in,
                              void* d_out, int out_size)
{
    const float* x    = (const float*)d_in[0];
    const float* wq   = (const float*)d_in[1];
    const float* bq   = (const float*)d_in[2];
    const float* wk   = (const float*)d_in[3];
    const float* bk   = (const float*)d_in[4];
    const float* wv   = (const float*)d_in[5];
    const float* bv   = (const float*)d_in[6];
    const float* wo   = (const float*)d_in[7];
    const float* bo   = (const float*)d_in[8];
    const void*  mask = (const void*)d_in[9];
    float* out = (float*)d_out;

    __half *xh, *xl, *wqh, *wkh, *wvh, *woh, *ah, *al;
    cudaGetSymbolAddress((void**)&xh, g_xh);
    cudaGetSymbolAddress((void**)&xl, g_xl);
    cudaGetSymbolAddress((void**)&wqh, g_wqh);
    cudaGetSymbolAddress((void**)&wkh, g_wkh);
    cudaGetSymbolAddress((void**)&wvh, g_wvh);
    cudaGetSymbolAddress((void**)&woh, g_woh);
    cudaGetSymbolAddress((void**)&ah, g_ah);
    cudaGetSymbolAddress((void**)&al, g_al);

    cudaFuncSetAttribute(gemm_f16_kernel,
                         cudaFuncAttributeMaxDynamicSharedMemorySize, GEMM_SMEM);
    cudaFuncSetAttribute(sparse_attn_mma_kernel,
                         cudaFuncAttributeMaxDynamicSharedMemorySize, AT_SMEM);

    build_blockmask_kernel<<<1, 64>>>(mask);

    const int nx4 = S * H / 4;
    const int nw4 = H * H / 4;
    split_f16_kernel<<<nx4 / 256, 256>>>(x, xh, xl, nx4);
    conv_f16_kernel<<<nw4 / 256, 256>>>(wq, wqh, nw4);
    conv_f16_kernel<<<nw4 / 256, 256>>>(wk, wkh, nw4);
    conv_f16_kernel<<<nw4 / 256, 256>>>(wv, wvh, nw4);
    conv_f16_kernel<<<nw4 / 256, 256>>>(wo, woh, nw4);

    // Fused QKV projection: 384 CTAs, writes q (pair) / k / v fp16
    dim3 qkvGrid(12, S / 128);
    gemm_f16_kernel<<<qkvGrid, 512, GEMM_SMEM>>>(xh, xl, bq, bk, bv, nullptr);

    dim3 attnGrid(NB, NH);
    sparse_attn_mma_kernel<<<attnGrid, 128, AT_SMEM>>>();

    // O projection: fp32 output
    dim3 oGrid(4, S / 128);
    gemm_f16_kernel<<<oGrid, 512, GEMM_SMEM>>>(ah, al, bo, nullptr, nullptr, out);
}

// round 17
// speedup vs baseline: 6.1349x; 1.0643x over previous
#include <cuda_runtime.h>
#include <cuda_fp16.h>
#include <cstdint>
#include <math.h>

// Problem constants
#define S    4096
#define H    1024
#define NH   16
#define HD   64
#define BS   64
#define NB   (S / BS)
#define KDIM 1024

// ---------------------------------------------------------------------------
// Scratch (device globals; no allocation allowed)
// ---------------------------------------------------------------------------
__device__ unsigned char g_cols[NB][NB];
__device__ int g_cnt[NB];

__device__ __align__(16) __half g_xh[S * H];
__device__ __align__(16) __half g_xl[S * H];
__device__ __align__(16) __half g_wqh[H * H];
__device__ __align__(16) __half g_wkh[H * H];
__device__ __align__(16) __half g_wvh[H * H];
__device__ __align__(16) __half g_woh[H * H];
__device__ __align__(16) __half g_qsh[S * H];
__device__ __align__(16) __half g_qsl[S * H];
__device__ __align__(16) __half g_ksh[S * H];
__device__ __align__(16) __half g_vsh[S * H];
__device__ __align__(16) __half g_ah[S * H];
__device__ __align__(16) __half g_al[S * H];

// ---------------------------------------------------------------------------
// Baseline-PTX primitives (sm_80+ ISA, compiles at compute_103)
// ---------------------------------------------------------------------------
__device__ __forceinline__ uint32_t smem_u32(const void* p) {
    uint32_t a;
    asm("{ .reg .u64 t; cvta.to.shared.u64 t, %1; cvt.u32.u64 %0, t; }"
        : "=r"(a) : "l"(p));
    return a;
}
__device__ __forceinline__ void ldsm_x4(uint32_t* r, uint32_t addr) {
    asm volatile("ldmatrix.sync.aligned.m8n8.x4.shared.b16 {%0,%1,%2,%3}, [%4];"
                 : "=r"(r[0]), "=r"(r[1]), "=r"(r[2]), "=r"(r[3]) : "r"(addr));
}
__device__ __forceinline__ void ldsm_x4_trans(uint32_t* r, uint32_t addr) {
    asm volatile("ldmatrix.sync.aligned.m8n8.x4.trans.shared.b16 {%0,%1,%2,%3}, [%4];"
                 : "=r"(r[0]), "=r"(r[1]), "=r"(r[2]), "=r"(r[3]) : "r"(addr));
}
__device__ __forceinline__ void mma_f16(float* d, const uint32_t* a,
                                        uint32_t b0, uint32_t b1) {
    asm volatile(
        "mma.sync.aligned.m16n8k16.row.col.f32.f16.f16.f32 "
        "{%0,%1,%2,%3}, {%4,%5,%6,%7}, {%8,%9}, {%0,%1,%2,%3};"
        : "+f"(d[0]), "+f"(d[1]), "+f"(d[2]), "+f"(d[3])
        : "r"(a[0]), "r"(a[1]), "r"(a[2]), "r"(a[3]), "r"(b0), "r"(b1));
}
__device__ __forceinline__ void cp_async16(uint32_t dst, const void* src) {
    asm volatile("cp.async.cg.shared.global [%0], [%1], 16;"
                 :: "r"(dst), "l"(src) : "memory");
}
#define CP_COMMIT() asm volatile("cp.async.commit_group;" ::: "memory")
#define CP_WAIT(n)  asm volatile("cp.async.wait_group %0;" :: "n"(n) : "memory")

// split v0,v1 -> fp16 hi pair word + fp16 lo pair word
__device__ __forceinline__ void split2h(float v0, float v1,
                                        uint32_t& hw, uint32_t& lw) {
    __half h0 = __float2half(v0);
    __half h1 = __float2half(v1);
    __half2 hh(h0, h1);
    hw = *(uint32_t*)&hh;
    __half2 ll(__float2half(v0 - __half2float(h0)),
               __float2half(v1 - __half2float(h1)));
    lw = *(uint32_t*)&ll;
}
__device__ __forceinline__ uint32_t pack_h2(float x, float y) {
    __half2 h = __floats2half2_rn(x, y);
    return *(uint32_t*)&h;
}
// packed fp16x2 exp2 (one MUFU op for two probabilities)
__device__ __forceinline__ uint32_t ex2_h2(uint32_t a) {
    uint32_t d;
    asm("ex2.approx.f16x2 %0, %1;" : "=r"(d) : "r"(a));
    return d;
}

// ---------------------------------------------------------------------------
// Block mask -> per-qblock active column lists (ballot-parallel)
// Grid: 64 blocks x 32 threads; block i scans q-block row i.
// ---------------------------------------------------------------------------
__global__ void build_blockmask_kernel(const void* __restrict__ mask) {
    const int i    = blockIdx.x;
    const int lane = threadIdx.x;

    unsigned int w0 = *(const unsigned int*)mask;
    int mode;
    if (w0 == 0x3F800000u)      mode = 0;
    else if (w0 == 0x01010101u) mode = 1;
    else if (w0 == 0x3F803F80u) mode = 2;
    else                        mode = 3;

    auto test = [&](int j) -> bool {
        size_t idx = (size_t)(i * BS) * S + (size_t)(j * BS);
        if (mode == 0)      return ((const float*)mask)[idx] != 0.0f;
        else if (mode == 1) return ((const unsigned char*)mask)[idx] != 0;
        else if (mode == 2) return (((const unsigned short*)mask)[idx] & 0x7FFFu) != 0;
        else                return ((const int*)mask)[idx] != 0;
    };

    unsigned int b0 = __ballot_sync(0xffffffffu, test(lane));
    unsigned int b1 = __ballot_sync(0xffffffffu, test(lane + 32));
    if (lane == 0) {
        int cnt = 0;
        for (int j = 0; j < 32; j++) if ((b0 >> j) & 1) g_cols[i][cnt++] = (unsigned char)j;
        for (int j = 0; j < 32; j++) if ((b1 >> j) & 1) g_cols[i][cnt++] = (unsigned char)(j + 32);
        g_cnt[i] = cnt;
    }
}

// ---------------------------------------------------------------------------
// Fused prep: x -> fp16 hi/lo split; 4 weight matrices -> fp16.
// Grid covers 2M float4 quads.
// ---------------------------------------------------------------------------
#define NX4 (S * H / 4)     // 1048576
#define NW4 (H * H / 4)     //  262144

__global__ __launch_bounds__(256) void prep_kernel(
    const float* __restrict__ x,
    const float* __restrict__ wq, const float* __restrict__ wk,
    const float* __restrict__ wv, const float* __restrict__ wo)
{
    int i = blockIdx.x * 256 + threadIdx.x;
    if (i < NX4) {
        float4 v = ((const float4*)x)[i];
        uint32_t h0, l0, h1, l1;
        split2h(v.x, v.y, h0, l0);
        split2h(v.z, v.w, h1, l1);
        ((uint32_t*)g_xh)[2 * i + 0] = h0;
        ((uint32_t*)g_xh)[2 * i + 1] = h1;
        ((uint32_t*)g_xl)[2 * i + 0] = l0;
        ((uint32_t*)g_xl)[2 * i + 1] = l1;
    } else {
        int j   = i - NX4;                 // 0 .. 4*NW4-1
        int sel = j >> 18;                 // NW4 = 2^18
        int idx = j & (NW4 - 1);
        const float* src = (sel == 0) ? wq : (sel == 1) ? wk : (sel == 2) ? wv : wo;
        __half* dst = (sel == 0) ? g_wqh : (sel == 1) ? g_wkh : (sel == 2) ? g_wvh : g_woh;
        float4 v = ((const float4*)src)[idx];
        ((uint32_t*)dst)[2 * idx + 0] = pack_h2(v.x, v.y);
        ((uint32_t*)dst)[2 * idx + 1] = pack_h2(v.z, v.w);
    }
}

// ---------------------------------------------------------------------------
// fp16 2-term GEMM core: C = A @ B^T + bias, terms Ah@Bh + Al@Bh.
// CTA tile 128x256, 512 threads = 16 warps (4 M x 4 N), warp tile 32x64.
// 3-stage cp.async pipeline, k-tile 32, pitch 40.  (unchanged, passing)
// ---------------------------------------------------------------------------
#define KT      32
#define PITCH   40
#define NKT     (KDIM / KT)                 // 32
#define TA      (128 * PITCH * 2)           // 10240 B
#define TB      (256 * PITCH * 2)           // 20480 B
#define STAGEB  (2 * TA + TB)               // 40960 B
#define GEMM_SMEM (3 * STAGEB)              // 122880 B

__global__ __launch_bounds__(512) void gemm_f16_kernel(
    const __half* __restrict__ Ah, const __half* __restrict__ Al,
    const float* __restrict__ b0, const float* __restrict__ b1,
    const float* __restrict__ b2,
    float* __restrict__ out32)
{
    extern __shared__ __align__(16) char gsm[];
    const uint32_t smem0 = smem_u32(gsm);

    const int tid  = threadIdx.x;
    const int lane = tid & 31;
    const int wid  = tid >> 5;
    const int wm   = wid & 3;
    const int wn   = wid >> 2;
    const int by   = blockIdx.y;

    int mat, bxn;
    const __half* Bh;
    const float* bias;
    if (out32) {
        mat = 3; bxn = blockIdx.x;
        Bh = g_woh; bias = b0;
    } else {
        mat = blockIdx.x >> 2; bxn = blockIdx.x & 3;
        Bh = (mat == 0) ? g_wqh : (mat == 1) ? g_wkh : g_wvh;
        bias = (mat == 0) ? b0 : (mat == 1) ? b1 : b2;
    }

    float acc[2][8][4];
    #pragma unroll
    for (int i = 0; i < 2; i++)
        #pragma unroll
        for (int j = 0; j < 8; j++)
            #pragma unroll
            for (int c = 0; c < 4; c++) acc[i][j][c] = 0.0f;

    const uint32_t a_row  = wm * 32 + (lane & 15);
    const uint32_t a_koff = ((lane >> 4) << 3);
    const uint32_t b_row  = wn * 64 + ((lane >> 3) & 1) * 8 + (lane & 7);
    const uint32_t b_koff = ((lane >> 4) << 3);

    auto load_stage = [&](int kt, int st) {
        const uint32_t sbase = smem0 + st * STAGEB;
        #pragma unroll
        for (int it = 0; it < 4; it++) {
            int f = tid + it * 512;
            if (f < 1024) {
                int arr = f >> 9;
                int idx = f & 511;
                int row = idx >> 2;
                int ch  = idx & 3;
                const __half* gb = (arr == 0 ? Ah : Al);
                cp_async16(sbase + arr * TA + (row * PITCH + ch * 8) * 2,
                           gb + (size_t)(by * 128 + row) * KDIM + kt * KT + ch * 8);
            } else {
                int idx = f - 1024;
                int row = idx >> 2;
                int ch  = idx & 3;
                cp_async16(sbase + 2 * TA + (row * PITCH + ch * 8) * 2,
                           Bh + (size_t)(bxn * 256 + row) * KDIM + kt * KT + ch * 8);
            }
        }
    };

    load_stage(0, 0); CP_COMMIT();
    load_stage(1, 1); CP_COMMIT();

    for (int kt = 0; kt < NKT; kt++) {
        if (kt == NKT - 1) { CP_WAIT(0); } else { CP_WAIT(1); }
        __syncthreads();

        if (kt + 2 < NKT) { load_stage(kt + 2, (kt + 2) % 3); CP_COMMIT(); }

        const uint32_t sb   = smem0 + (kt % 3) * STAGEB;
        const uint32_t sA_h = sb;
        const uint32_t sA_l = sb + TA;
        const uint32_t sB_h = sb + 2 * TA;

        #pragma unroll
        for (int kk = 0; kk < 2; kk++) {
            const uint32_t k0 = kk * 16;

            uint32_t ah[2][4], al[2][4];
            #pragma unroll
            for (int mt = 0; mt < 2; mt++) {
                uint32_t off = ((a_row + mt * 16) * PITCH + k0 + a_koff) * 2;
                ldsm_x4(ah[mt], sA_h + off);
                ldsm_x4(al[mt], sA_l + off);
            }
            uint32_t bh[4][4];
            #pragma unroll
            for (int nt2 = 0; nt2 < 4; nt2++) {
                uint32_t off = ((b_row + nt2 * 16) * PITCH + k0 + b_koff) * 2;
                ldsm_x4(bh[nt2], sB_h + off);
            }

            #pragma unroll
            for (int mt = 0; mt < 2; mt++)
                #pragma unroll
                for (int nt = 0; nt < 8; nt++) {
                    const int g = nt >> 1, h = nt & 1;
                    mma_f16(acc[mt][nt], ah[mt], bh[g][h], bh[g][h + 2]);
                    mma_f16(acc[mt][nt], al[mt], bh[g][h], bh[g][h + 2]);
                }
        }
    }

    const int m0 = by * 128 + wm * 32 + (lane >> 2);
    const int n0 = bxn * 256 + wn * 64 + (lane & 3) * 2;
    #pragma unroll
    for (int mt = 0; mt < 2; mt++) {
        const int r0 = m0 + mt * 16;
        #pragma unroll
        for (int nt = 0; nt < 8; nt++) {
            const int col = n0 + nt * 8;
            const float bb0 = bias[col], bb1 = bias[col + 1];
            const float v00 = acc[mt][nt][0] + bb0, v01 = acc[mt][nt][1] + bb1;
            const float v10 = acc[mt][nt][2] + bb0, v11 = acc[mt][nt][3] + bb1;
            if (mat == 3) {
                *(float2*)(out32 + (size_t)r0 * H + col)       = make_float2(v00, v01);
                *(float2*)(out32 + (size_t)(r0 + 8) * H + col) = make_float2(v10, v11);
            } else if (mat == 0) {
                uint32_t hw, lw;
                split2h(v00, v01, hw, lw);
                *(uint32_t*)(g_qsh + (size_t)r0 * H + col) = hw;
                *(uint32_t*)(g_qsl + (size_t)r0 * H + col) = lw;
                split2h(v10, v11, hw, lw);
                *(uint32_t*)(g_qsh + (size_t)(r0 + 8) * H + col) = hw;
                *(uint32_t*)(g_qsl + (size_t)(r0 + 8) * H + col) = lw;
            } else {
                __half* dst = (mat == 1) ? g_ksh : g_vsh;
                *(uint32_t*)(dst + (size_t)r0 * H + col)       = pack_h2(v00, v01);
                *(uint32_t*)(dst + (size_t)(r0 + 8) * H + col) = pack_h2(v10, v11);
            }
        }
    }
}

// ---------------------------------------------------------------------------
// Block-sparse flash attention: fp16 mma, f16x2-MUFU softmax.
// Grid: (NB, NH). 128 threads = 4 warps; warp handles 16 q-rows x 64 cols.
// QK 2-term (Qh+Ql); P computed directly in packed fp16 via ex2.approx.f16x2
// (halves MUFU ops, P regs are the PV A-fragments); PV single-term.
// ---------------------------------------------------------------------------
#define APITCH   72
#define KVTILE   (64 * APITCH * 2)       // 9216 B
#define AT_SMEM  (2 * 2 * KVTILE)        // 36864 B

__global__ __launch_bounds__(128) void sparse_attn_mma_kernel()
{
    extern __shared__ __align__(16) char asmem[];
    const uint32_t sb0 = smem_u32(asmem);

    const int qb   = blockIdx.x;
    const int head = blockIdx.y;
    const int tid  = threadIdx.x;
    const int lane = tid & 31;
    const int wid  = tid >> 5;
    const int g    = lane >> 2;
    const int t    = lane & 3;

    const float SCALE = 0.125f * 1.44269504088896340736f;

    const int r0 = qb * BS + wid * 16;
    const int cb = head * HD;

    uint32_t qhf[4][4], qlf[4][4];
    #pragma unroll
    for (int kk = 0; kk < 4; kk++) {
        const int c0 = cb + kk * 16 + 2 * t;
        qhf[kk][0] = *(const uint32_t*)&g_qsh[(size_t)(r0 + g) * H + c0];
        qhf[kk][1] = *(const uint32_t*)&g_qsh[(size_t)(r0 + g + 8) * H + c0];
        qhf[kk][2] = *(const uint32_t*)&g_qsh[(size_t)(r0 + g) * H + c0 + 8];
        qhf[kk][3] = *(const uint32_t*)&g_qsh[(size_t)(r0 + g + 8) * H + c0 + 8];
        qlf[kk][0] = *(const uint32_t*)&g_qsl[(size_t)(r0 + g) * H + c0];
        qlf[kk][1] = *(const uint32_t*)&g_qsl[(size_t)(r0 + g + 8) * H + c0];
        qlf[kk][2] = *(const uint32_t*)&g_qsl[(size_t)(r0 + g) * H + c0 + 8];
        qlf[kk][3] = *(const uint32_t*)&g_qsl[(size_t)(r0 + g + 8) * H + c0 + 8];
    }

    const uint32_t b_rowl = ((lane >> 3) & 1) * 8 + (lane & 7);
    const uint32_t b_koff = (lane >> 4) * 8;

    float O[8][4];
    #pragma unroll
    for (int j = 0; j < 8; j++)
        #pragma unroll
        for (int c = 0; c < 4; c++) O[j][c] = 0.0f;
    float m1 = -INFINITY, m2 = -INFINITY, l1 = 0.0f, l2 = 0.0f;

    const int cnt = g_cnt[qb];

    auto load_stage = [&](int jblk, int st) {
        const int kr0 = jblk * BS;
        const uint32_t sbase = sb0 + st * 2 * KVTILE;
        #pragma unroll
        for (int it = 0; it < 8; it++) {
            int f    = tid + it * 128;
            int arr  = f >> 9;
            int row  = (f >> 3) & 63;
            int ch   = f & 7;
            const __half* gb = arr == 0 ? g_ksh : g_vsh;
            cp_async16(sbase + arr * KVTILE + (row * APITCH + ch * 8) * 2,
                       gb + (size_t)(kr0 + row) * H + cb + ch * 8);
        }
    };

    load_stage(g_cols[qb][0], 0); CP_COMMIT();

    for (int jj = 0; jj < cnt; jj++) {
        const int st = jj & 1;
        if (jj + 1 < cnt) { load_stage(g_cols[qb][jj + 1], st ^ 1); CP_COMMIT(); }
        if (jj + 1 < cnt) { CP_WAIT(1); } else { CP_WAIT(0); }
        __syncthreads();

        const uint32_t sKh = sb0 + st * 2 * KVTILE;
        const uint32_t sVh = sKh + KVTILE;

        float sacc[8][4];
        #pragma unroll
        for (int j = 0; j < 8; j++)
            #pragma unroll
            for (int c = 0; c < 4; c++) sacc[j][c] = 0.0f;

        #pragma unroll
        for (int kk = 0; kk < 4; kk++) {
            uint32_t kh[4][4];
            #pragma unroll
            for (int g4 = 0; g4 < 4; g4++) {
                uint32_t off = ((g4 * 16 + b_rowl) * APITCH + kk * 16 + b_koff) * 2;
                ldsm_x4(kh[g4], sKh + off);
            }
            #pragma unroll
            for (int nt = 0; nt < 8; nt++) {
                const int g4 = nt >> 1, h = nt & 1;
                mma_f16(sacc[nt], qhf[kk], kh[g4][h], kh[g4][h + 2]);
                mma_f16(sacc[nt], qlf[kk], kh[g4][h], kh[g4][h + 2]);
            }
        }

        #pragma unroll
        for (int j = 0; j < 8; j++)
            #pragma unroll
            for (int c = 0; c < 4; c++) sacc[j][c] *= SCALE;

        float mx1 = sacc[0][0], mx2 = sacc[0][2];
        #pragma unroll
        for (int j = 0; j < 8; j++) {
            mx1 = fmaxf(mx1, fmaxf(sacc[j][0], sacc[j][1]));
            mx2 = fmaxf(mx2, fmaxf(sacc[j][2], sacc[j][3]));
        }
        mx1 = fmaxf(mx1, __shfl_xor_sync(0xffffffffu, mx1, 1));
        mx1 = fmaxf(mx1, __shfl_xor_sync(0xffffffffu, mx1, 2));
        mx2 = fmaxf(mx2, __shfl_xor_sync(0xffffffffu, mx2, 1));
        mx2 = fmaxf(mx2, __shfl_xor_sync(0xffffffffu, mx2, 2));

        const float mn1 = fmaxf(m1, mx1);
        const float mn2 = fmaxf(m2, mx2);
        const float al1 = exp2f(m1 - mn1);
        const float al2 = exp2f(m2 - mn2);
        m1 = mn1; m2 = mn2;

        // P in packed fp16 via one MUFU op per pair; fp32 row sums
        uint32_t pf[8][2];
        float ls1 = 0.0f, ls2 = 0.0f;
        #pragma unroll
        for (int j = 0; j < 8; j++) {
            pf[j][0] = ex2_h2(pack_h2(sacc[j][0] - mn1, sacc[j][1] - mn1));
            pf[j][1] = ex2_h2(pack_h2(sacc[j][2] - mn2, sacc[j][3] - mn2));
            float2 f0 = __half22float2(*(__half2*)&pf[j][0]);
            float2 f1 = __half22float2(*(__half2*)&pf[j][1]);
            ls1 += f0.x + f0.y;
            ls2 += f1.x + f1.y;
        }
        ls1 += __shfl_xor_sync(0xffffffffu, ls1, 1);
        ls1 += __shfl_xor_sync(0xffffffffu, ls1, 2);
        ls2 += __shfl_xor_sync(0xffffffffu, ls2, 1);
        ls2 += __shfl_xor_sync(0xffffffffu, ls2, 2);
        l1 = l1 * al1 + ls1;
        l2 = l2 * al2 + ls2;

        #pragma unroll
        for (int j = 0; j < 8; j++) {
            O[j][0] *= al1; O[j][1] *= al1;
            O[j][2] *= al2; O[j][3] *= al2;
        }

        // O += P @ V (single term; pf regs are the A-fragments)
        #pragma unroll
        for (int kk = 0; kk < 4; kk++) {
            uint32_t pah[4] = { pf[2 * kk][0], pf[2 * kk][1],
                                pf[2 * kk + 1][0], pf[2 * kk + 1][1] };
            #pragma unroll
            for (int nj = 0; nj < 4; nj++) {
                uint32_t vh[4];
                uint32_t off = ((kk * 16 + b_rowl) * APITCH + nj * 16 + b_koff) * 2;
                ldsm_x4_trans(vh, sVh + off);
                mma_f16(O[2 * nj + 0], pah, vh[0], vh[1]);
                mma_f16(O[2 * nj + 1], pah, vh[2], vh[3]);
            }
        }
        __syncthreads();
    }

    // finalize + store hi/lo split for the O-projection
    const float i1 = 1.0f / l1;
    const float i2 = 1.0f / l2;
    #pragma unroll
    for (int j = 0; j < 8; j++) {
        const int col = cb + 8 * j + 2 * t;
        uint32_t hw, lw;
        split2h(O[j][0] * i1, O[j][1] * i1, hw, lw);
        *(uint32_t*)(g_ah + (size_t)(r0 + g) * H + col) = hw;
        *(uint32_t*)(g_al + (size_t)(r0 + g) * H + col) = lw;
        split2h(O[j][2] * i2, O[j][3] * i2, hw, lw);
        *(uint32_t*)(g_ah + (size_t)(r0 + g + 8) * H + col) = hw;
        *(uint32_t*)(g_al + (size_t)(r0 + g + 8) * H + col) = lw;
    }
}

// ---------------------------------------------------------------------------
// Launch
// Inputs (metadata order): hidden_states, wq, bq, wk, bk, wv, bv, wo, bo, mask
// ---------------------------------------------------------------------------
extern "C" void kernel_launch(void* const* d_in, const int* in_sizes, int n_in,
                              void* d_out, int out_size)
{
    const float* x    = (const float*)d_in[0];
    const float* wq   = (const float*)d_in[1];
    const float* bq   = (const float*)d_in[2];
    const float* wk   = (const float*)d_in[3];
    const float* bk   = (const float*)d_in[4];
    const float* wv   = (const float*)d_in[5];
    const float* bv   = (const float*)d_in[6];
    const float* wo   = (const float*)d_in[7];
    const float* bo   = (const float*)d_in[8];
    const void*  mask = (const void*)d_in[9];
    float* out = (float*)d_out;

    __half *xh, *xl, *ah, *al;
    cudaGetSymbolAddress((void**)&xh, g_xh);
    cudaGetSymbolAddress((void**)&xl, g_xl);
    cudaGetSymbolAddress((void**)&ah, g_ah);
    cudaGetSymbolAddress((void**)&al, g_al);

    cudaFuncSetAttribute(gemm_f16_kernel,
                         cudaFuncAttributeMaxDynamicSharedMemorySize, GEMM_SMEM);
    cudaFuncSetAttribute(sparse_attn_mma_kernel,
                         cudaFuncAttributeMaxDynamicSharedMemorySize, AT_SMEM);

    build_blockmask_kernel<<<NB, 32>>>(mask);
    prep_kernel<<<(NX4 + 4 * NW4) / 256, 256>>>(x, wq, wk, wv, wo);

    // Fused QKV projection: 384 CTAs, writes q (pair) / k / v fp16
    dim3 qkvGrid(12, S / 128);
    gemm_f16_kernel<<<qkvGrid, 512, GEMM_SMEM>>>(xh, xl, bq, bk, bv, nullptr);

    dim3 attnGrid(NB, NH);
    sparse_attn_mma_kernel<<<attnGrid, 128, AT_SMEM>>>();

    // O projection: fp32 output
    dim3 oGrid(4, S / 128);
    gemm_f16_kernel<<<oGrid, 512, GEMM_SMEM>>>(ah, al, bo, nullptr, nullptr, out);
}